// round 2
// baseline (speedup 1.0000x reference)
#include <cuda_runtime.h>
#include <math_constants.h>

// ---------------- problem constants ----------------
#define N_NODES 20000
#define N_EDGES 320000
#define F_IN    256
#define HIDC    64
#define HEADS   8
#define NCLS    64
#define HC1     (HEADS*HIDC)      // 512
#define NEG_SLOPE 0.2f
#define SM_EPS  1e-16f

// ---------------- scratch (static device globals; no allocs) ----------------
__device__ float g_xlr1[(size_t)N_NODES * 1024];   // [N][xl1(512) | xr1(512)]
__device__ float g_h[(size_t)N_NODES * HC1];       // layer-1 output after ELU
__device__ float g_xlr2[(size_t)N_NODES * 128];    // [N][xl2(64) | xr2(64)]
__device__ int   g_deg[N_NODES];
__device__ int   g_off[N_NODES + 1];
__device__ int   g_cur[N_NODES];
__device__ int   g_perm[N_EDGES];

// ---------------- CSR build ----------------
__global__ void hist_kernel(const int* __restrict__ dst) {
    int e = blockIdx.x * blockDim.x + threadIdx.x;
    if (e < N_EDGES) atomicAdd(&g_deg[dst[e]], 1);
}

__global__ void scan_kernel() {
    __shared__ int sums[1024];
    const int CH = (N_NODES + 1023) / 1024;  // 20
    int t = threadIdx.x;
    int base = t * CH;
    int s = 0;
    for (int i = 0; i < CH; i++) {
        int idx = base + i;
        if (idx < N_NODES) s += g_deg[idx];
    }
    sums[t] = s;
    __syncthreads();
    for (int d = 1; d < 1024; d <<= 1) {
        int v = (t >= d) ? sums[t - d] : 0;
        __syncthreads();
        sums[t] += v;
        __syncthreads();
    }
    int pre = (t == 0) ? 0 : sums[t - 1];
    for (int i = 0; i < CH; i++) {
        int idx = base + i;
        if (idx < N_NODES) {
            g_off[idx] = pre;
            g_cur[idx] = pre;
            pre += g_deg[idx];
        }
    }
    if (t == 0) g_off[N_NODES] = sums[1023];
}

__global__ void scatter_kernel(const int* __restrict__ dst) {
    int e = blockIdx.x * blockDim.x + threadIdx.x;
    if (e < N_EDGES) {
        int p = atomicAdd(&g_cur[dst[e]], 1);
        g_perm[p] = e;
    }
}

// ---------------- fp32 GEMM, 128x128 tile, 8x8 register blocking, BK=8 ----------------
// C[m, cofs+n] = sum_k A[m,k]*B[k,n]; A row-major [M,K], B row-major [K,Nn].
__global__ void __launch_bounds__(256) sgemm128_kernel(
    int M, int Nn, int K,
    const float* __restrict__ A, const float* __restrict__ B,
    float* __restrict__ C, int ldc, int cofs)
{
    const int BM = 128, BN = 128, BK = 8, TM = 8, TN = 8;
    __shared__ float As[BK][BM];
    __shared__ float Bs[BK][BN];

    const int tid  = threadIdx.x;
    const int tcol = tid % (BN / TN);   // 16
    const int trow = tid / (BN / TN);   // 16
    const int by = blockIdx.y, bx = blockIdx.x;

    float acc[TM][TN];
#pragma unroll
    for (int i = 0; i < TM; i++)
#pragma unroll
        for (int j = 0; j < TN; j++) acc[i][j] = 0.f;

    for (int k0 = 0; k0 < K; k0 += BK) {
        // A tile: 128 rows x 8 k. Each thread: one float4 along K.
        {
            int r  = tid >> 1;             // 0..127
            int kk = (tid & 1) * 4;        // 0 or 4
            int grow = by * BM + r;
            float4 v = make_float4(0.f, 0.f, 0.f, 0.f);
            if (grow < M) v = *(const float4*)(A + (size_t)grow * K + k0 + kk);
            As[kk + 0][r] = v.x;
            As[kk + 1][r] = v.y;
            As[kk + 2][r] = v.z;
            As[kk + 3][r] = v.w;
        }
        // B tile: 8 rows x 128 n. Each thread: one float4 along N.
        {
            int r  = tid >> 5;             // 0..7
            int nn = (tid & 31) * 4;       // 0..124
            float4 v = *(const float4*)(B + (size_t)(k0 + r) * Nn + bx * BN + nn);
            *(float4*)&Bs[r][nn] = v;
        }
        __syncthreads();

#pragma unroll
        for (int k = 0; k < BK; k++) {
            float ra[TM], rb[TN];
#pragma unroll
            for (int i = 0; i < TM; i += 4)
                *(float4*)&ra[i] = *(const float4*)&As[k][trow * TM + i];
#pragma unroll
            for (int j = 0; j < TN; j += 4)
                *(float4*)&rb[j] = *(const float4*)&Bs[k][tcol * TN + j];
#pragma unroll
            for (int i = 0; i < TM; i++)
#pragma unroll
                for (int j = 0; j < TN; j++) acc[i][j] += ra[i] * rb[j];
        }
        __syncthreads();
    }

#pragma unroll
    for (int i = 0; i < TM; i++) {
        int grow = by * BM + trow * TM + i;
        if (grow < M) {
#pragma unroll
            for (int j = 0; j < TN; j += 4) {
                float4 v = make_float4(acc[i][j], acc[i][j+1], acc[i][j+2], acc[i][j+3]);
                *(float4*)(C + (size_t)grow * ldc + cofs + bx * BN + tcol * TN + j) = v;
            }
        }
    }
}

// ---------------- fp32 tiled GEMM (layer-2 sizes): 128x64, BK=16, 8x4 ----------------
template <int BM, int BN, int BK, int TM, int TN>
__global__ void __launch_bounds__(256) sgemm_kernel(
    int M, int Nn, int K,
    const float* __restrict__ A, const float* __restrict__ B,
    float* __restrict__ C, int ldc, int cofs)
{
    __shared__ float As[BK][BM];
    __shared__ float Bs[BK][BN];

    const int tid  = threadIdx.x;
    const int tcol = tid % (BN / TN);
    const int trow = tid / (BN / TN);
    const int by = blockIdx.y, bx = blockIdx.x;

    float acc[TM][TN];
#pragma unroll
    for (int i = 0; i < TM; i++)
#pragma unroll
        for (int j = 0; j < TN; j++) acc[i][j] = 0.f;

    for (int k0 = 0; k0 < K; k0 += BK) {
#pragma unroll
        for (int i = 0; i < (BM * BK) / (256 * 4); i++) {
            int f  = tid + 256 * i;
            int r  = f / (BK / 4);
            int kk = (f % (BK / 4)) * 4;
            int grow = by * BM + r;
            float4 v = make_float4(0.f, 0.f, 0.f, 0.f);
            if (grow < M) v = *(const float4*)(A + (size_t)grow * K + k0 + kk);
            As[kk + 0][r] = v.x;
            As[kk + 1][r] = v.y;
            As[kk + 2][r] = v.z;
            As[kk + 3][r] = v.w;
        }
#pragma unroll
        for (int i = 0; i < (BK * BN) / (256 * 4); i++) {
            int f  = tid + 256 * i;
            int r  = f / (BN / 4);
            int nn = (f % (BN / 4)) * 4;
            float4 v = *(const float4*)(B + (size_t)(k0 + r) * Nn + bx * BN + nn);
            *(float4*)&Bs[r][nn] = v;
        }
        __syncthreads();

#pragma unroll
        for (int k = 0; k < BK; k++) {
            float ra[TM], rb[TN];
#pragma unroll
            for (int i = 0; i < TM; i += 4)
                *(float4*)&ra[i] = *(const float4*)&As[k][trow * TM + i];
#pragma unroll
            for (int j = 0; j < TN; j += 4)
                *(float4*)&rb[j] = *(const float4*)&Bs[k][tcol * TN + j];
#pragma unroll
            for (int i = 0; i < TM; i++)
#pragma unroll
                for (int j = 0; j < TN; j++) acc[i][j] += ra[i] * rb[j];
        }
        __syncthreads();
    }

#pragma unroll
    for (int i = 0; i < TM; i++) {
        int grow = by * BM + trow * TM + i;
        if (grow < M) {
            float4 v = make_float4(acc[i][0], acc[i][1], acc[i][2], acc[i][3]);
            *(float4*)(C + (size_t)grow * ldc + cofs + bx * BN + tcol * TN) = v;
        }
    }
}

// ---------------- layer 1: fused score + online softmax + aggregate + bias + ELU ----------------
// one block per node; warp h handles head h (64 channels, 2 per lane)
__global__ void __launch_bounds__(256) node1_fused_kernel(
    const int* __restrict__ src, const float* __restrict__ att1,
    const float* __restrict__ b1)
{
    int n = blockIdx.x;
    int h = threadIdx.x >> 5, lane = threadIdx.x & 31;
    int beg = g_off[n], end = g_off[n + 1];
    int c0 = h * 64 + lane;

    // target-side projection for this node/head (resident in regs)
    float xr0 = g_xlr1[(size_t)n * 1024 + 512 + c0];
    float xr1 = g_xlr1[(size_t)n * 1024 + 512 + c0 + 32];
    float at0 = att1[c0], at1 = att1[c0 + 32];

    float m = -CUDART_INF_F, ssum = 0.f;
    float acc0 = 0.f, acc1 = 0.f;

    for (int i = beg; i < end; i++) {
        int e = g_perm[i];
        const float* p = g_xlr1 + (size_t)src[e] * 1024 + h * 64;
        float x0 = p[lane], x1 = p[lane + 32];
        float u0 = x0 + xr0; u0 = u0 > 0.f ? u0 : NEG_SLOPE * u0;
        float u1 = x1 + xr1; u1 = u1 > 0.f ? u1 : NEG_SLOPE * u1;
        float s = at0 * u0 + at1 * u1;
#pragma unroll
        for (int o = 16; o; o >>= 1) s += __shfl_xor_sync(0xffffffffu, s, o);
        float mn = fmaxf(m, s);
        float scale = __expf(m - mn);     // exp(-inf)=0 on first edge
        float es = __expf(s - mn);
        ssum = ssum * scale + es;
        acc0 = acc0 * scale + es * x0;
        acc1 = acc1 * scale + es * x1;
        m = mn;
    }

    float inv = 1.f / (ssum + SM_EPS);
    float v0 = acc0 * inv + b1[c0];
    float v1 = acc1 * inv + b1[c0 + 32];
    g_h[(size_t)n * HC1 + c0]      = v0 > 0.f ? v0 : __expf(v0) - 1.f;
    g_h[(size_t)n * HC1 + c0 + 32] = v1 > 0.f ? v1 : __expf(v1) - 1.f;
}

// ---------------- layer 2: fused score + online softmax + aggregate + bias -> out ----------------
// one warp per node (64 channels, 2 per lane)
__global__ void __launch_bounds__(256) node2_fused_kernel(
    const int* __restrict__ src, const float* __restrict__ att2,
    const float* __restrict__ b2, float* __restrict__ out)
{
    int n = blockIdx.x * 8 + (threadIdx.x >> 5);
    if (n >= N_NODES) return;
    int lane = threadIdx.x & 31;
    int beg = g_off[n], end = g_off[n + 1];

    float xr0 = g_xlr2[(size_t)n * 128 + 64 + lane];
    float xr1 = g_xlr2[(size_t)n * 128 + 64 + lane + 32];
    float at0 = att2[lane], at1 = att2[lane + 32];

    float m = -CUDART_INF_F, ssum = 0.f;
    float acc0 = 0.f, acc1 = 0.f;

    for (int i = beg; i < end; i++) {
        int e = g_perm[i];
        const float* p = g_xlr2 + (size_t)src[e] * 128;
        float x0 = p[lane], x1 = p[lane + 32];
        float u0 = x0 + xr0; u0 = u0 > 0.f ? u0 : NEG_SLOPE * u0;
        float u1 = x1 + xr1; u1 = u1 > 0.f ? u1 : NEG_SLOPE * u1;
        float s = at0 * u0 + at1 * u1;
#pragma unroll
        for (int o = 16; o; o >>= 1) s += __shfl_xor_sync(0xffffffffu, s, o);
        float mn = fmaxf(m, s);
        float scale = __expf(m - mn);
        float es = __expf(s - mn);
        ssum = ssum * scale + es;
        acc0 = acc0 * scale + es * x0;
        acc1 = acc1 * scale + es * x1;
        m = mn;
    }

    float inv = 1.f / (ssum + SM_EPS);
    out[(size_t)n * NCLS + lane]      = acc0 * inv + b2[lane];
    out[(size_t)n * NCLS + lane + 32] = acc1 * inv + b2[lane + 32];
}

// ---------------- launch ----------------
extern "C" void kernel_launch(void* const* d_in, const int* in_sizes, int n_in,
                              void* d_out, int out_size)
{
    (void)in_sizes; (void)n_in; (void)out_size;
    const float* x    = (const float*)d_in[0];
    const int*   ei   = (const int*)d_in[1];
    const int*   src  = ei;
    const int*   dst  = ei + N_EDGES;
    const float* Wl1  = (const float*)d_in[2];
    const float* Wr1  = (const float*)d_in[3];
    const float* att1 = (const float*)d_in[4];
    const float* b1   = (const float*)d_in[5];
    const float* Wl2  = (const float*)d_in[6];
    const float* Wr2  = (const float*)d_in[7];
    const float* att2 = (const float*)d_in[8];
    const float* b2   = (const float*)d_in[9];
    float* out = (float*)d_out;

    void *p_deg, *p_xlr1, *p_h, *p_xlr2;
    cudaGetSymbolAddress(&p_deg, g_deg);
    cudaGetSymbolAddress(&p_xlr1, g_xlr1);
    cudaGetSymbolAddress(&p_h, g_h);
    cudaGetSymbolAddress(&p_xlr2, g_xlr2);

    // CSR build
    cudaMemsetAsync(p_deg, 0, N_NODES * sizeof(int), 0);
    hist_kernel<<<(N_EDGES + 255) / 256, 256>>>(dst);
    scan_kernel<<<1, 1024>>>();
    scatter_kernel<<<(N_EDGES + 255) / 256, 256>>>(dst);

    // layer-1 projections: xl1 | xr1 -> g_xlr1 [N,1024]
    {
        dim3 grid(HC1 / 128, (N_NODES + 127) / 128);
        sgemm128_kernel<<<grid, 256>>>(N_NODES, HC1, F_IN, x, Wl1, (float*)p_xlr1, 1024, 0);
        sgemm128_kernel<<<grid, 256>>>(N_NODES, HC1, F_IN, x, Wr1, (float*)p_xlr1, 1024, 512);
    }
    node1_fused_kernel<<<N_NODES, 256>>>(src, att1, b1);

    // layer-2 projections: xl2 | xr2 -> g_xlr2 [N,128]
    {
        dim3 grid(1, (N_NODES + 127) / 128);
        sgemm_kernel<128, 64, 16, 8, 4><<<grid, 256>>>(
            N_NODES, NCLS, HC1, (const float*)p_h, Wl2, (float*)p_xlr2, 128, 0);
        sgemm_kernel<128, 64, 16, 8, 4><<<grid, 256>>>(
            N_NODES, NCLS, HC1, (const float*)p_h, Wr2, (float*)p_xlr2, 128, 64);
    }
    node2_fused_kernel<<<(N_NODES + 7) / 8, 256>>>(src, att2, b2, out);
}

// round 3
// speedup vs baseline: 2.0700x; 2.0700x over previous
#include <cuda_runtime.h>
#include <math_constants.h>

// ---------------- problem constants ----------------
#define N_NODES 20000
#define N_EDGES 320000
#define F_IN    256
#define HIDC    64
#define HEADS   8
#define NCLS    64
#define HC1     (HEADS*HIDC)      // 512
#define NEG_SLOPE 0.2f
#define SM_EPS  1e-16f

typedef unsigned long long u64;

__device__ __forceinline__ void fma2(u64& d, u64 a, u64 b) {
    asm("fma.rn.f32x2 %0, %1, %2, %0;" : "+l"(d) : "l"(a), "l"(b));
}
__device__ __forceinline__ u64 dup2(float x) {
    u64 r; asm("mov.b64 %0, {%1, %1};" : "=l"(r) : "f"(x)); return r;
}
__device__ __forceinline__ void unpack2(u64 v, float& lo, float& hi) {
    asm("mov.b64 {%0, %1}, %2;" : "=f"(lo), "=f"(hi) : "l"(v));
}

// ---------------- scratch (static device globals; no allocs) ----------------
__device__ float g_xlr1[(size_t)N_NODES * 1024];   // [N][xl1(512) | xr1(512)]
__device__ float g_h[(size_t)N_NODES * HC1];       // layer-1 output after ELU
__device__ float g_xlr2[(size_t)N_NODES * 128];    // [N][xl2(64) | xr2(64)]
__device__ int   g_deg[N_NODES];
__device__ int   g_off[N_NODES + 1];
__device__ int   g_cur[N_NODES];
__device__ int   g_perm[N_EDGES];

// ---------------- CSR build ----------------
__global__ void hist_kernel(const int* __restrict__ dst) {
    int e = blockIdx.x * blockDim.x + threadIdx.x;
    if (e < N_EDGES) atomicAdd(&g_deg[dst[e]], 1);
}

__global__ void scan_kernel() {
    __shared__ int sums[1024];
    const int CH = (N_NODES + 1023) / 1024;  // 20
    int t = threadIdx.x;
    int base = t * CH;
    int s = 0;
    for (int i = 0; i < CH; i++) {
        int idx = base + i;
        if (idx < N_NODES) s += g_deg[idx];
    }
    sums[t] = s;
    __syncthreads();
    for (int d = 1; d < 1024; d <<= 1) {
        int v = (t >= d) ? sums[t - d] : 0;
        __syncthreads();
        sums[t] += v;
        __syncthreads();
    }
    int pre = (t == 0) ? 0 : sums[t - 1];
    for (int i = 0; i < CH; i++) {
        int idx = base + i;
        if (idx < N_NODES) {
            g_off[idx] = pre;
            g_cur[idx] = pre;
            pre += g_deg[idx];
        }
    }
    if (t == 0) g_off[N_NODES] = sums[1023];
}

__global__ void scatter_kernel(const int* __restrict__ dst) {
    int e = blockIdx.x * blockDim.x + threadIdx.x;
    if (e < N_EDGES) {
        int p = atomicAdd(&g_cur[dst[e]], 1);
        g_perm[p] = e;
    }
}

// ---------------- fp32 GEMM with packed f32x2 FMAs ----------------
// BM=128, BN=64, BK=16; per-thread 8x4, rows paired into f32x2.
// grid.z selects (B0,cofs0) vs (B1,cofs1): computes C[m, cofs+n] = A@B.
__global__ void __launch_bounds__(256) sgemm2_kernel(
    int M, int Nn, int K,
    const float* __restrict__ A,
    const float* __restrict__ B0, const float* __restrict__ B1,
    float* __restrict__ C, int ldc, int cofs0, int cofs1)
{
    const int BM = 128, BN = 64, BK = 16, TM = 8, TN = 4;
    const float* B = blockIdx.z ? B1 : B0;
    const int cofs = blockIdx.z ? cofs1 : cofs0;

    __shared__ float As[BK][BM];
    __shared__ float Bs[BK][BN];

    const int tid  = threadIdx.x;
    const int tcol = tid % (BN / TN);   // 16
    const int trow = tid / (BN / TN);   // 16
    const int by = blockIdx.y, bx = blockIdx.x;

    u64 acc[TM / 2][TN];                // pairs along TM
#pragma unroll
    for (int i = 0; i < TM / 2; i++)
#pragma unroll
        for (int j = 0; j < TN; j++) acc[i][j] = 0ull;

    for (int k0 = 0; k0 < K; k0 += BK) {
        // A tile (BM x BK), float4 along K
#pragma unroll
        for (int it = 0; it < (BM * BK) / (256 * 4); it++) {
            int f  = tid + 256 * it;
            int r  = f / (BK / 4);
            int kk = (f % (BK / 4)) * 4;
            int grow = by * BM + r;
            float4 v = make_float4(0.f, 0.f, 0.f, 0.f);
            if (grow < M) v = *(const float4*)(A + (size_t)grow * K + k0 + kk);
            As[kk + 0][r] = v.x;
            As[kk + 1][r] = v.y;
            As[kk + 2][r] = v.z;
            As[kk + 3][r] = v.w;
        }
        // B tile (BK x BN), float4 along N
        {
            int r  = tid / (BN / 4);        // 0..15
            int nn = (tid % (BN / 4)) * 4;  // 0..60
            float4 v = *(const float4*)(B + (size_t)(k0 + r) * Nn + bx * BN + nn);
            *(float4*)&Bs[r][nn] = v;
        }
        __syncthreads();

#pragma unroll
        for (int k = 0; k < BK; k++) {
            // ra: 8 consecutive rows -> 4 f32x2 pairs (natural, 32B-aligned)
            ulonglong2 rlo = *(const ulonglong2*)&As[k][trow * TM];
            ulonglong2 rhi = *(const ulonglong2*)&As[k][trow * TM + 4];
            u64 ra[4] = { rlo.x, rlo.y, rhi.x, rhi.y };
            float4 b4 = *(const float4*)&Bs[k][tcol * TN];
            u64 rb[4] = { dup2(b4.x), dup2(b4.y), dup2(b4.z), dup2(b4.w) };
#pragma unroll
            for (int i = 0; i < TM / 2; i++)
#pragma unroll
                for (int j = 0; j < TN; j++) fma2(acc[i][j], ra[i], rb[j]);
        }
        __syncthreads();
    }

#pragma unroll
    for (int i = 0; i < TM / 2; i++) {
        float r0[TN], r1[TN];
#pragma unroll
        for (int j = 0; j < TN; j++) unpack2(acc[i][j], r0[j], r1[j]);
        int grow = by * BM + trow * TM + 2 * i;
        float* cp = C + (size_t)grow * ldc + cofs + bx * BN + tcol * TN;
        if (grow < M)     *(float4*)cp               = make_float4(r0[0], r0[1], r0[2], r0[3]);
        if (grow + 1 < M) *(float4*)(cp + ldc)       = make_float4(r1[0], r1[1], r1[2], r1[3]);
    }
}

// ---------------- layer 1: fused score + online softmax + aggregate + bias + ELU ----------------
// one block per node; warp h handles head h (64 channels, 2 per lane); edge loop unrolled x4
__global__ void __launch_bounds__(256) node1_fused_kernel(
    const int* __restrict__ src, const float* __restrict__ att1,
    const float* __restrict__ b1)
{
    int n = blockIdx.x;
    int h = threadIdx.x >> 5, lane = threadIdx.x & 31;
    int beg = g_off[n], end = g_off[n + 1];
    int c0 = h * 64 + lane;

    float xr0 = g_xlr1[(size_t)n * 1024 + 512 + c0];
    float xr1 = g_xlr1[(size_t)n * 1024 + 512 + c0 + 32];
    float at0 = att1[c0], at1 = att1[c0 + 32];

    float m = -CUDART_INF_F, ssum = 0.f;
    float acc0 = 0.f, acc1 = 0.f;

    int i = beg;
    for (; i + 4 <= end; i += 4) {
        const float* p0 = g_xlr1 + (size_t)src[g_perm[i + 0]] * 1024 + h * 64;
        const float* p1 = g_xlr1 + (size_t)src[g_perm[i + 1]] * 1024 + h * 64;
        const float* p2 = g_xlr1 + (size_t)src[g_perm[i + 2]] * 1024 + h * 64;
        const float* p3 = g_xlr1 + (size_t)src[g_perm[i + 3]] * 1024 + h * 64;
        float a0 = p0[lane], b0 = p0[lane + 32];
        float a1 = p1[lane], b1v = p1[lane + 32];
        float a2 = p2[lane], b2v = p2[lane + 32];
        float a3 = p3[lane], b3v = p3[lane + 32];

        float u, v;
        u = a0 + xr0; u = u > 0.f ? u : NEG_SLOPE * u;
        v = b0 + xr1; v = v > 0.f ? v : NEG_SLOPE * v;
        float s0 = at0 * u + at1 * v;
        u = a1 + xr0; u = u > 0.f ? u : NEG_SLOPE * u;
        v = b1v + xr1; v = v > 0.f ? v : NEG_SLOPE * v;
        float s1 = at0 * u + at1 * v;
        u = a2 + xr0; u = u > 0.f ? u : NEG_SLOPE * u;
        v = b2v + xr1; v = v > 0.f ? v : NEG_SLOPE * v;
        float s2 = at0 * u + at1 * v;
        u = a3 + xr0; u = u > 0.f ? u : NEG_SLOPE * u;
        v = b3v + xr1; v = v > 0.f ? v : NEG_SLOPE * v;
        float s3 = at0 * u + at1 * v;

#pragma unroll
        for (int o = 16; o; o >>= 1) {
            s0 += __shfl_xor_sync(0xffffffffu, s0, o);
            s1 += __shfl_xor_sync(0xffffffffu, s1, o);
            s2 += __shfl_xor_sync(0xffffffffu, s2, o);
            s3 += __shfl_xor_sync(0xffffffffu, s3, o);
        }

        float mn = fmaxf(fmaxf(fmaxf(s0, s1), fmaxf(s2, s3)), m);
        float scale = __expf(m - mn);
        float w0 = __expf(s0 - mn), w1 = __expf(s1 - mn);
        float w2 = __expf(s2 - mn), w3 = __expf(s3 - mn);
        ssum = ssum * scale + ((w0 + w1) + (w2 + w3));
        acc0 = acc0 * scale + ((w0 * a0 + w1 * a1) + (w2 * a2 + w3 * a3));
        acc1 = acc1 * scale + ((w0 * b0 + w1 * b1v) + (w2 * b2v + w3 * b3v));
        m = mn;
    }
    for (; i < end; i++) {
        const float* p = g_xlr1 + (size_t)src[g_perm[i]] * 1024 + h * 64;
        float x0 = p[lane], x1 = p[lane + 32];
        float u = x0 + xr0; u = u > 0.f ? u : NEG_SLOPE * u;
        float v = x1 + xr1; v = v > 0.f ? v : NEG_SLOPE * v;
        float s = at0 * u + at1 * v;
#pragma unroll
        for (int o = 16; o; o >>= 1) s += __shfl_xor_sync(0xffffffffu, s, o);
        float mn = fmaxf(m, s);
        float scale = __expf(m - mn);
        float es = __expf(s - mn);
        ssum = ssum * scale + es;
        acc0 = acc0 * scale + es * x0;
        acc1 = acc1 * scale + es * x1;
        m = mn;
    }

    float inv = 1.f / (ssum + SM_EPS);
    float v0 = acc0 * inv + b1[c0];
    float v1 = acc1 * inv + b1[c0 + 32];
    g_h[(size_t)n * HC1 + c0]      = v0 > 0.f ? v0 : __expf(v0) - 1.f;
    g_h[(size_t)n * HC1 + c0 + 32] = v1 > 0.f ? v1 : __expf(v1) - 1.f;
}

// ---------------- layer 2: fused, one warp per node, unrolled x4 ----------------
__global__ void __launch_bounds__(256) node2_fused_kernel(
    const int* __restrict__ src, const float* __restrict__ att2,
    const float* __restrict__ b2, float* __restrict__ out)
{
    int n = blockIdx.x * 8 + (threadIdx.x >> 5);
    if (n >= N_NODES) return;
    int lane = threadIdx.x & 31;
    int beg = g_off[n], end = g_off[n + 1];

    float xr0 = g_xlr2[(size_t)n * 128 + 64 + lane];
    float xr1 = g_xlr2[(size_t)n * 128 + 64 + lane + 32];
    float at0 = att2[lane], at1 = att2[lane + 32];

    float m = -CUDART_INF_F, ssum = 0.f;
    float acc0 = 0.f, acc1 = 0.f;

    int i = beg;
    for (; i + 4 <= end; i += 4) {
        const float* p0 = g_xlr2 + (size_t)src[g_perm[i + 0]] * 128;
        const float* p1 = g_xlr2 + (size_t)src[g_perm[i + 1]] * 128;
        const float* p2 = g_xlr2 + (size_t)src[g_perm[i + 2]] * 128;
        const float* p3 = g_xlr2 + (size_t)src[g_perm[i + 3]] * 128;
        float a0 = p0[lane], b0 = p0[lane + 32];
        float a1 = p1[lane], b1v = p1[lane + 32];
        float a2 = p2[lane], b2v = p2[lane + 32];
        float a3 = p3[lane], b3v = p3[lane + 32];

        float u, v;
        u = a0 + xr0; u = u > 0.f ? u : NEG_SLOPE * u;
        v = b0 + xr1; v = v > 0.f ? v : NEG_SLOPE * v;
        float s0 = at0 * u + at1 * v;
        u = a1 + xr0; u = u > 0.f ? u : NEG_SLOPE * u;
        v = b1v + xr1; v = v > 0.f ? v : NEG_SLOPE * v;
        float s1 = at0 * u + at1 * v;
        u = a2 + xr0; u = u > 0.f ? u : NEG_SLOPE * u;
        v = b2v + xr1; v = v > 0.f ? v : NEG_SLOPE * v;
        float s2 = at0 * u + at1 * v;
        u = a3 + xr0; u = u > 0.f ? u : NEG_SLOPE * u;
        v = b3v + xr1; v = v > 0.f ? v : NEG_SLOPE * v;
        float s3 = at0 * u + at1 * v;

#pragma unroll
        for (int o = 16; o; o >>= 1) {
            s0 += __shfl_xor_sync(0xffffffffu, s0, o);
            s1 += __shfl_xor_sync(0xffffffffu, s1, o);
            s2 += __shfl_xor_sync(0xffffffffu, s2, o);
            s3 += __shfl_xor_sync(0xffffffffu, s3, o);
        }

        float mn = fmaxf(fmaxf(fmaxf(s0, s1), fmaxf(s2, s3)), m);
        float scale = __expf(m - mn);
        float w0 = __expf(s0 - mn), w1 = __expf(s1 - mn);
        float w2 = __expf(s2 - mn), w3 = __expf(s3 - mn);
        ssum = ssum * scale + ((w0 + w1) + (w2 + w3));
        acc0 = acc0 * scale + ((w0 * a0 + w1 * a1) + (w2 * a2 + w3 * a3));
        acc1 = acc1 * scale + ((w0 * b0 + w1 * b1v) + (w2 * b2v + w3 * b3v));
        m = mn;
    }
    for (; i < end; i++) {
        const float* p = g_xlr2 + (size_t)src[g_perm[i]] * 128;
        float x0 = p[lane], x1 = p[lane + 32];
        float u = x0 + xr0; u = u > 0.f ? u : NEG_SLOPE * u;
        float v = x1 + xr1; v = v > 0.f ? v : NEG_SLOPE * v;
        float s = at0 * u + at1 * v;
#pragma unroll
        for (int o = 16; o; o >>= 1) s += __shfl_xor_sync(0xffffffffu, s, o);
        float mn = fmaxf(m, s);
        float scale = __expf(m - mn);
        float es = __expf(s - mn);
        ssum = ssum * scale + es;
        acc0 = acc0 * scale + es * x0;
        acc1 = acc1 * scale + es * x1;
        m = mn;
    }

    float inv = 1.f / (ssum + SM_EPS);
    out[(size_t)n * NCLS + lane]      = acc0 * inv + b2[lane];
    out[(size_t)n * NCLS + lane + 32] = acc1 * inv + b2[lane + 32];
}

// ---------------- launch ----------------
extern "C" void kernel_launch(void* const* d_in, const int* in_sizes, int n_in,
                              void* d_out, int out_size)
{
    (void)in_sizes; (void)n_in; (void)out_size;
    const float* x    = (const float*)d_in[0];
    const int*   ei   = (const int*)d_in[1];
    const int*   src  = ei;
    const int*   dst  = ei + N_EDGES;
    const float* Wl1  = (const float*)d_in[2];
    const float* Wr1  = (const float*)d_in[3];
    const float* att1 = (const float*)d_in[4];
    const float* b1   = (const float*)d_in[5];
    const float* Wl2  = (const float*)d_in[6];
    const float* Wr2  = (const float*)d_in[7];
    const float* att2 = (const float*)d_in[8];
    const float* b2   = (const float*)d_in[9];
    float* out = (float*)d_out;

    void *p_deg, *p_xlr1, *p_h, *p_xlr2;
    cudaGetSymbolAddress(&p_deg, g_deg);
    cudaGetSymbolAddress(&p_xlr1, g_xlr1);
    cudaGetSymbolAddress(&p_h, g_h);
    cudaGetSymbolAddress(&p_xlr2, g_xlr2);

    // CSR build
    cudaMemsetAsync(p_deg, 0, N_NODES * sizeof(int), 0);
    hist_kernel<<<(N_EDGES + 255) / 256, 256>>>(dst);
    scan_kernel<<<1, 1024>>>();
    scatter_kernel<<<(N_EDGES + 255) / 256, 256>>>(dst);

    // layer-1 projections: xl1 | xr1 -> g_xlr1 [N,1024] (one launch, z picks Wl/Wr)
    {
        dim3 grid(HC1 / 64, (N_NODES + 127) / 128, 2);
        sgemm2_kernel<<<grid, 256>>>(N_NODES, HC1, F_IN, x, Wl1, Wr1,
                                     (float*)p_xlr1, 1024, 0, 512);
    }
    node1_fused_kernel<<<N_NODES, 256>>>(src, att1, b1);

    // layer-2 projections: xl2 | xr2 -> g_xlr2 [N,128]
    {
        dim3 grid(NCLS / 64, (N_NODES + 127) / 128, 2);
        sgemm2_kernel<<<grid, 256>>>(N_NODES, NCLS, HC1, (const float*)p_h, Wl2, Wr2,
                                     (float*)p_xlr2, 128, 0, 64);
    }
    node2_fused_kernel<<<(N_NODES + 7) / 8, 256>>>(src, att2, b2, out);
}

// round 6
// speedup vs baseline: 2.4447x; 1.1810x over previous
#include <cuda_runtime.h>
#include <cuda_bf16.h>
#include <math_constants.h>
#include <cstdint>

// ---------------- problem constants ----------------
#define N_NODES 20000
#define N_EDGES 320000
#define F_IN    256
#define HIDC    64
#define HEADS   8
#define NCLS    64
#define HC1     (HEADS*HIDC)      // 512
#define NEG_SLOPE 0.2f
#define SM_EPS  1e-16f

typedef unsigned long long u64;

// ---------------- scratch (static device globals; no allocs) ----------------
__device__ float g_xlr1[(size_t)N_NODES * 1024];   // [N][xl1(512) | xr1(512)]
__device__ float g_xlr2[(size_t)N_NODES * 128];    // [N][xl2(64) | xr2(64)]
__device__ int   g_deg[N_NODES];
__device__ int   g_off[N_NODES + 1];
__device__ int   g_cur[N_NODES];
__device__ int   g_perm[N_EDGES];

// bf16 split operands
__device__ __nv_bfloat16 g_xhi[(size_t)N_NODES * F_IN];
__device__ __nv_bfloat16 g_xlo[(size_t)N_NODES * F_IN];
__device__ __nv_bfloat16 g_hhi[(size_t)N_NODES * HC1];   // written by node1 epilogue
__device__ __nv_bfloat16 g_hlo[(size_t)N_NODES * HC1];
__device__ __nv_bfloat16 g_wt1hi[1024 * 256];   // [Ntot=1024][K=256] (W^T, K-contig)
__device__ __nv_bfloat16 g_wt1lo[1024 * 256];
__device__ __nv_bfloat16 g_wt2hi[128 * 512];    // [Ntot=128][K=512]
__device__ __nv_bfloat16 g_wt2lo[128 * 512];

// ---------------- helpers ----------------
__device__ __forceinline__ uint32_t smem_u32(const void* p) {
    uint32_t a;
    asm("{ .reg .u64 t; cvta.to.shared.u64 t, %1; cvt.u32.u64 %0, t; }" : "=r"(a) : "l"(p));
    return a;
}
#define SWZ128(o) ((o) ^ (((o) >> 3) & 0x70))

__device__ __forceinline__ void ldmx4(uint32_t* r, uint32_t addr) {
    asm volatile("ldmatrix.sync.aligned.m8n8.x4.shared.b16 {%0,%1,%2,%3}, [%4];"
                 : "=r"(r[0]), "=r"(r[1]), "=r"(r[2]), "=r"(r[3]) : "r"(addr));
}
__device__ __forceinline__ void mma16816(float* c, const uint32_t* a, uint32_t b0, uint32_t b1) {
    asm volatile("mma.sync.aligned.m16n8k16.row.col.f32.bf16.bf16.f32 "
                 "{%0,%1,%2,%3}, {%4,%5,%6,%7}, {%8,%9}, {%0,%1,%2,%3};"
                 : "+f"(c[0]), "+f"(c[1]), "+f"(c[2]), "+f"(c[3])
                 : "r"(a[0]), "r"(a[1]), "r"(a[2]), "r"(a[3]), "r"(b0), "r"(b1));
}

// ---------------- CSR build ----------------
__global__ void hist_kernel(const int* __restrict__ dst) {
    int e = blockIdx.x * blockDim.x + threadIdx.x;
    if (e < N_EDGES) atomicAdd(&g_deg[dst[e]], 1);
}

__global__ void scan_kernel() {
    __shared__ int sums[1024];
    const int CH = (N_NODES + 1023) / 1024;
    int t = threadIdx.x;
    int base = t * CH;
    int s = 0;
    for (int i = 0; i < CH; i++) {
        int idx = base + i;
        if (idx < N_NODES) s += g_deg[idx];
    }
    sums[t] = s;
    __syncthreads();
    for (int d = 1; d < 1024; d <<= 1) {
        int v = (t >= d) ? sums[t - d] : 0;
        __syncthreads();
        sums[t] += v;
        __syncthreads();
    }
    int pre = (t == 0) ? 0 : sums[t - 1];
    for (int i = 0; i < CH; i++) {
        int idx = base + i;
        if (idx < N_NODES) {
            g_off[idx] = pre;
            g_cur[idx] = pre;
            pre += g_deg[idx];
        }
    }
    if (t == 0) g_off[N_NODES] = sums[1023];
}

__global__ void scatter_kernel(const int* __restrict__ dst) {
    int e = blockIdx.x * blockDim.x + threadIdx.x;
    if (e < N_EDGES) {
        int p = atomicAdd(&g_cur[dst[e]], 1);
        g_perm[p] = e;
    }
}

// ---------------- bf16 split kernels ----------------
__global__ void split_kernel(const float* __restrict__ src,
                             __nv_bfloat16* __restrict__ hi,
                             __nv_bfloat16* __restrict__ lo, int n) {
    int i = blockIdx.x * blockDim.x + threadIdx.x;
    if (i < n) {
        float v = src[i];
        __nv_bfloat16 h = __float2bfloat16(v);
        hi[i] = h;
        lo[i] = __float2bfloat16(v - __bfloat162float(h));
    }
}

// W0,W1: [K, N0] row-major each -> Wt [2*N0, K] (row n = col n of W0 for n<N0 else W1)
__global__ void wtsplit_kernel(const float* __restrict__ W0, const float* __restrict__ W1,
                               int K, int N0,
                               __nv_bfloat16* __restrict__ hi,
                               __nv_bfloat16* __restrict__ lo) {
    int i = blockIdx.x * blockDim.x + threadIdx.x;
    if (i >= 2 * N0 * K) return;
    int n = i / K, k = i % K;
    float v = (n < N0) ? W0[(size_t)k * N0 + n] : W1[(size_t)k * N0 + (n - N0)];
    __nv_bfloat16 h = __float2bfloat16(v);
    hi[(size_t)n * K + k] = h;
    lo[(size_t)n * K + k] = __float2bfloat16(v - __bfloat162float(h));
}

// ---------------- mma.sync split-bf16 GEMM ----------------
// C[by*128+r, bx*64+n] = sum_k A[r,k]*B[n,k];  A=[M,K] hi/lo, B=[Ntot,K] hi/lo (K-contig).
// CTA tile 128x64, K-chunk 64. 8 warps in 4x2 (warp tile 32x32). 3-product split.
#define SM_AHI  0
#define SM_ALO  16384
#define SM_BHI  32768
#define SM_BLO  40960
#define SM_TOT  49152

__global__ void __launch_bounds__(256) gemm_mma_kernel(
    int M, int K, int ldc,
    const __nv_bfloat16* __restrict__ Ahi, const __nv_bfloat16* __restrict__ Alo,
    const __nv_bfloat16* __restrict__ Bhi, const __nv_bfloat16* __restrict__ Blo,
    float* __restrict__ C)
{
    extern __shared__ char smem[];
    uint32_t sb = smem_u32(smem);
    const int tid = threadIdx.x, wid = tid >> 5, lane = tid & 31;
    const int by = blockIdx.y, bx = blockIdx.x;
    const int warpM = wid & 3, warpN = wid >> 2;   // 4 x 2 warp grid

    float acc[2][4][4];   // [m16 tile][n8 frag][4]
#pragma unroll
    for (int a = 0; a < 2; a++)
#pragma unroll
        for (int b = 0; b < 4; b++)
#pragma unroll
            for (int c = 0; c < 4; c++) acc[a][b][c] = 0.f;

    const int nchunks = K >> 6;
    for (int ch = 0; ch < nchunks; ch++) {
        int k0 = ch << 6;
        // A tiles: 128 rows x 64 bf16 (hi+lo), swizzled 128B rows
        for (int i = tid; i < 2048; i += 256) {
            int row = i >> 4, g = (i & 15) << 2;
            int gr = by * 128 + row;
            uint32_t so = SWZ128(row * 128 + g * 2);
            u64 vh = 0, vl = 0;
            if (gr < M) {
                vh = *(const u64*)(Ahi + (size_t)gr * K + k0 + g);
                vl = *(const u64*)(Alo + (size_t)gr * K + k0 + g);
            }
            *(u64*)(smem + SM_AHI + so) = vh;
            *(u64*)(smem + SM_ALO + so) = vl;
        }
        // B tiles: 64 rows x 64 bf16 (hi+lo)
        for (int i = tid; i < 1024; i += 256) {
            int row = i >> 4, g = (i & 15) << 2;
            int gn = bx * 64 + row;
            uint32_t so = SWZ128(row * 128 + g * 2);
            *(u64*)(smem + SM_BHI + so) = *(const u64*)(Bhi + (size_t)gn * K + k0 + g);
            *(u64*)(smem + SM_BLO + so) = *(const u64*)(Blo + (size_t)gn * K + k0 + g);
        }
        __syncthreads();

#pragma unroll
        for (int ks = 0; ks < 4; ks++) {
            uint32_t ahi[2][4], alo[2][4], bhi[2][4], blo[2][4];
            int colb = ks * 32 + (lane >> 4) * 16;   // byte col within 128B row
#pragma unroll
            for (int mt = 0; mt < 2; mt++) {
                uint32_t off = SWZ128((warpM * 32 + mt * 16 + (lane & 15)) * 128 + colb);
                ldmx4(ahi[mt], sb + SM_AHI + off);
                ldmx4(alo[mt], sb + SM_ALO + off);
            }
#pragma unroll
            for (int nt = 0; nt < 2; nt++) {
                uint32_t off = SWZ128((warpN * 32 + nt * 16 + (lane & 15)) * 128 + colb);
                ldmx4(bhi[nt], sb + SM_BHI + off);
                ldmx4(blo[nt], sb + SM_BLO + off);
            }
#pragma unroll
            for (int mt = 0; mt < 2; mt++)
#pragma unroll
                for (int nt = 0; nt < 2; nt++)
#pragma unroll
                    for (int hf = 0; hf < 2; hf++) {
                        float* c = acc[mt][nt * 2 + hf];
                        mma16816(c, ahi[mt], bhi[nt][hf], bhi[nt][hf + 2]);
                        mma16816(c, ahi[mt], blo[nt][hf], blo[nt][hf + 2]);
                        mma16816(c, alo[mt], bhi[nt][hf], bhi[nt][hf + 2]);
                    }
        }
        __syncthreads();
    }

    // epilogue: stage fp32 tile in smem (aliases A region), coalesced store
    float* stage = (float*)(smem + SM_AHI);
    {
        int r0 = lane >> 2, cb = (lane & 3) * 2;
#pragma unroll
        for (int mt = 0; mt < 2; mt++)
#pragma unroll
            for (int j = 0; j < 4; j++) {
                int col = warpN * 32 + (j >> 1) * 16 + (j & 1) * 8 + cb;
                float* st = stage + (warpM * 32 + mt * 16 + r0) * 64 + col;
                st[0]        = acc[mt][j][0];
                st[1]        = acc[mt][j][1];
                st[8 * 64]     = acc[mt][j][2];
                st[8 * 64 + 1] = acc[mt][j][3];
            }
    }
    __syncthreads();
    for (int i = tid; i < 2048; i += 256) {
        int row = i >> 4, c4 = (i & 15) << 2;
        int gr = by * 128 + row;
        if (gr < M)
            *(float4*)(C + (size_t)gr * ldc + bx * 64 + c4) = *(float4*)(stage + row * 64 + c4);
    }
}

// ---------------- layer 1: fused score + online softmax + aggregate + bias + ELU ----------------
// one block per node; warp h handles head h; writes bf16 hi/lo of ELU(h) directly
__global__ void __launch_bounds__(256) node1_fused_kernel(
    const int* __restrict__ src, const float* __restrict__ att1,
    const float* __restrict__ b1)
{
    int n = blockIdx.x;
    int h = threadIdx.x >> 5, lane = threadIdx.x & 31;
    int beg = g_off[n], end = g_off[n + 1];
    int c0 = h * 64 + lane;

    float xr0 = g_xlr1[(size_t)n * 1024 + 512 + c0];
    float xr1 = g_xlr1[(size_t)n * 1024 + 512 + c0 + 32];
    float at0 = att1[c0], at1 = att1[c0 + 32];

    float m = -CUDART_INF_F, ssum = 0.f;
    float acc0 = 0.f, acc1 = 0.f;

    int i = beg;
    for (; i + 4 <= end; i += 4) {
        const float* p0 = g_xlr1 + (size_t)src[g_perm[i + 0]] * 1024 + h * 64;
        const float* p1 = g_xlr1 + (size_t)src[g_perm[i + 1]] * 1024 + h * 64;
        const float* p2 = g_xlr1 + (size_t)src[g_perm[i + 2]] * 1024 + h * 64;
        const float* p3 = g_xlr1 + (size_t)src[g_perm[i + 3]] * 1024 + h * 64;
        float a0 = p0[lane], b0 = p0[lane + 32];
        float a1 = p1[lane], b1v = p1[lane + 32];
        float a2 = p2[lane], b2v = p2[lane + 32];
        float a3 = p3[lane], b3v = p3[lane + 32];

        float u, v;
        u = a0 + xr0; u = u > 0.f ? u : NEG_SLOPE * u;
        v = b0 + xr1; v = v > 0.f ? v : NEG_SLOPE * v;
        float s0 = at0 * u + at1 * v;
        u = a1 + xr0; u = u > 0.f ? u : NEG_SLOPE * u;
        v = b1v + xr1; v = v > 0.f ? v : NEG_SLOPE * v;
        float s1 = at0 * u + at1 * v;
        u = a2 + xr0; u = u > 0.f ? u : NEG_SLOPE * u;
        v = b2v + xr1; v = v > 0.f ? v : NEG_SLOPE * v;
        float s2 = at0 * u + at1 * v;
        u = a3 + xr0; u = u > 0.f ? u : NEG_SLOPE * u;
        v = b3v + xr1; v = v > 0.f ? v : NEG_SLOPE * v;
        float s3 = at0 * u + at1 * v;

#pragma unroll
        for (int o = 16; o; o >>= 1) {
            s0 += __shfl_xor_sync(0xffffffffu, s0, o);
            s1 += __shfl_xor_sync(0xffffffffu, s1, o);
            s2 += __shfl_xor_sync(0xffffffffu, s2, o);
            s3 += __shfl_xor_sync(0xffffffffu, s3, o);
        }

        float mn = fmaxf(fmaxf(fmaxf(s0, s1), fmaxf(s2, s3)), m);
        float scale = __expf(m - mn);
        float w0 = __expf(s0 - mn), w1 = __expf(s1 - mn);
        float w2 = __expf(s2 - mn), w3 = __expf(s3 - mn);
        ssum = ssum * scale + ((w0 + w1) + (w2 + w3));
        acc0 = acc0 * scale + ((w0 * a0 + w1 * a1) + (w2 * a2 + w3 * a3));
        acc1 = acc1 * scale + ((w0 * b0 + w1 * b1v) + (w2 * b2v + w3 * b3v));
        m = mn;
    }
    for (; i < end; i++) {
        const float* p = g_xlr1 + (size_t)src[g_perm[i]] * 1024 + h * 64;
        float x0 = p[lane], x1 = p[lane + 32];
        float u = x0 + xr0; u = u > 0.f ? u : NEG_SLOPE * u;
        float v = x1 + xr1; v = v > 0.f ? v : NEG_SLOPE * v;
        float s = at0 * u + at1 * v;
#pragma unroll
        for (int o = 16; o; o >>= 1) s += __shfl_xor_sync(0xffffffffu, s, o);
        float mn = fmaxf(m, s);
        float scale = __expf(m - mn);
        float es = __expf(s - mn);
        ssum = ssum * scale + es;
        acc0 = acc0 * scale + es * x0;
        acc1 = acc1 * scale + es * x1;
        m = mn;
    }

    float inv = 1.f / (ssum + SM_EPS);
    float v0 = acc0 * inv + b1[c0];
    float v1 = acc1 * inv + b1[c0 + 32];
    v0 = v0 > 0.f ? v0 : __expf(v0) - 1.f;
    v1 = v1 > 0.f ? v1 : __expf(v1) - 1.f;
    size_t o0 = (size_t)n * HC1 + c0, o1 = o0 + 32;
    __nv_bfloat16 h0 = __float2bfloat16(v0), h1 = __float2bfloat16(v1);
    g_hhi[o0] = h0; g_hlo[o0] = __float2bfloat16(v0 - __bfloat162float(h0));
    g_hhi[o1] = h1; g_hlo[o1] = __float2bfloat16(v1 - __bfloat162float(h1));
}

// ---------------- layer 2: fused, one warp per node, unrolled x4 ----------------
__global__ void __launch_bounds__(256) node2_fused_kernel(
    const int* __restrict__ src, const float* __restrict__ att2,
    const float* __restrict__ b2, float* __restrict__ out)
{
    int n = blockIdx.x * 8 + (threadIdx.x >> 5);
    if (n >= N_NODES) return;
    int lane = threadIdx.x & 31;
    int beg = g_off[n], end = g_off[n + 1];

    float xr0 = g_xlr2[(size_t)n * 128 + 64 + lane];
    float xr1 = g_xlr2[(size_t)n * 128 + 64 + lane + 32];
    float at0 = att2[lane], at1 = att2[lane + 32];

    float m = -CUDART_INF_F, ssum = 0.f;
    float acc0 = 0.f, acc1 = 0.f;

    int i = beg;
    for (; i + 4 <= end; i += 4) {
        const float* p0 = g_xlr2 + (size_t)src[g_perm[i + 0]] * 128;
        const float* p1 = g_xlr2 + (size_t)src[g_perm[i + 1]] * 128;
        const float* p2 = g_xlr2 + (size_t)src[g_perm[i + 2]] * 128;
        const float* p3 = g_xlr2 + (size_t)src[g_perm[i + 3]] * 128;
        float a0 = p0[lane], b0 = p0[lane + 32];
        float a1 = p1[lane], b1v = p1[lane + 32];
        float a2 = p2[lane], b2v = p2[lane + 32];
        float a3 = p3[lane], b3v = p3[lane + 32];

        float u, v;
        u = a0 + xr0; u = u > 0.f ? u : NEG_SLOPE * u;
        v = b0 + xr1; v = v > 0.f ? v : NEG_SLOPE * v;
        float s0 = at0 * u + at1 * v;
        u = a1 + xr0; u = u > 0.f ? u : NEG_SLOPE * u;
        v = b1v + xr1; v = v > 0.f ? v : NEG_SLOPE * v;
        float s1 = at0 * u + at1 * v;
        u = a2 + xr0; u = u > 0.f ? u : NEG_SLOPE * u;
        v = b2v + xr1; v = v > 0.f ? v : NEG_SLOPE * v;
        float s2 = at0 * u + at1 * v;
        u = a3 + xr0; u = u > 0.f ? u : NEG_SLOPE * u;
        v = b3v + xr1; v = v > 0.f ? v : NEG_SLOPE * v;
        float s3 = at0 * u + at1 * v;

#pragma unroll
        for (int o = 16; o; o >>= 1) {
            s0 += __shfl_xor_sync(0xffffffffu, s0, o);
            s1 += __shfl_xor_sync(0xffffffffu, s1, o);
            s2 += __shfl_xor_sync(0xffffffffu, s2, o);
            s3 += __shfl_xor_sync(0xffffffffu, s3, o);
        }

        float mn = fmaxf(fmaxf(fmaxf(s0, s1), fmaxf(s2, s3)), m);
        float scale = __expf(m - mn);
        float w0 = __expf(s0 - mn), w1 = __expf(s1 - mn);
        float w2 = __expf(s2 - mn), w3 = __expf(s3 - mn);
        ssum = ssum * scale + ((w0 + w1) + (w2 + w3));
        acc0 = acc0 * scale + ((w0 * a0 + w1 * a1) + (w2 * a2 + w3 * a3));
        acc1 = acc1 * scale + ((w0 * b0 + w1 * b1v) + (w2 * b2v + w3 * b3v));
        m = mn;
    }
    for (; i < end; i++) {
        const float* p = g_xlr2 + (size_t)src[g_perm[i]] * 128;
        float x0 = p[lane], x1 = p[lane + 32];
        float u = x0 + xr0; u = u > 0.f ? u : NEG_SLOPE * u;
        float v = x1 + xr1; v = v > 0.f ? v : NEG_SLOPE * v;
        float s = at0 * u + at1 * v;
#pragma unroll
        for (int o = 16; o; o >>= 1) s += __shfl_xor_sync(0xffffffffu, s, o);
        float mn = fmaxf(m, s);
        float scale = __expf(m - mn);
        float es = __expf(s - mn);
        ssum = ssum * scale + es;
        acc0 = acc0 * scale + es * x0;
        acc1 = acc1 * scale + es * x1;
        m = mn;
    }

    float inv = 1.f / (ssum + SM_EPS);
    out[(size_t)n * NCLS + lane]      = acc0 * inv + b2[lane];
    out[(size_t)n * NCLS + lane + 32] = acc1 * inv + b2[lane + 32];
}

// ---------------- launch ----------------
extern "C" void kernel_launch(void* const* d_in, const int* in_sizes, int n_in,
                              void* d_out, int out_size)
{
    (void)in_sizes; (void)n_in; (void)out_size;
    const float* x    = (const float*)d_in[0];
    const int*   ei   = (const int*)d_in[1];
    const int*   src  = ei;
    const int*   dst  = ei + N_EDGES;
    const float* Wl1  = (const float*)d_in[2];
    const float* Wr1  = (const float*)d_in[3];
    const float* att1 = (const float*)d_in[4];
    const float* b1   = (const float*)d_in[5];
    const float* Wl2  = (const float*)d_in[6];
    const float* Wr2  = (const float*)d_in[7];
    const float* att2 = (const float*)d_in[8];
    const float* b2   = (const float*)d_in[9];
    float* out = (float*)d_out;

    void *p_deg, *p_xlr1, *p_xlr2;
    void *p_xhi, *p_xlo, *p_hhi, *p_hlo, *p_w1h, *p_w1l, *p_w2h, *p_w2l;
    cudaGetSymbolAddress(&p_deg, g_deg);
    cudaGetSymbolAddress(&p_xlr1, g_xlr1);
    cudaGetSymbolAddress(&p_xlr2, g_xlr2);
    cudaGetSymbolAddress(&p_xhi, g_xhi);
    cudaGetSymbolAddress(&p_xlo, g_xlo);
    cudaGetSymbolAddress(&p_hhi, g_hhi);
    cudaGetSymbolAddress(&p_hlo, g_hlo);
    cudaGetSymbolAddress(&p_w1h, g_wt1hi);
    cudaGetSymbolAddress(&p_w1l, g_wt1lo);
    cudaGetSymbolAddress(&p_w2h, g_wt2hi);
    cudaGetSymbolAddress(&p_w2l, g_wt2lo);

    // CSR build
    cudaMemsetAsync(p_deg, 0, N_NODES * sizeof(int), 0);
    hist_kernel<<<(N_EDGES + 255) / 256, 256>>>(dst);
    scan_kernel<<<1, 1024>>>();
    scatter_kernel<<<(N_EDGES + 255) / 256, 256>>>(dst);

    // split x and weights (layer 1)
    split_kernel<<<(N_NODES * F_IN + 255) / 256, 256>>>(
        x, (__nv_bfloat16*)p_xhi, (__nv_bfloat16*)p_xlo, N_NODES * F_IN);
    wtsplit_kernel<<<(1024 * 256 + 255) / 256, 256>>>(
        Wl1, Wr1, 256, 512, (__nv_bfloat16*)p_w1h, (__nv_bfloat16*)p_w1l);

    // layer-1 projections via mma.sync: g_xlr1 [N,1024]
    {
        dim3 grid(1024 / 64, (N_NODES + 127) / 128);
        gemm_mma_kernel<<<grid, 256, SM_TOT>>>(
            N_NODES, 256, 1024,
            (const __nv_bfloat16*)p_xhi, (const __nv_bfloat16*)p_xlo,
            (const __nv_bfloat16*)p_w1h, (const __nv_bfloat16*)p_w1l,
            (float*)p_xlr1);
    }
    node1_fused_kernel<<<N_NODES, 256>>>(src, att1, b1);

    // weights (layer 2)
    wtsplit_kernel<<<(128 * 512 + 255) / 256, 256>>>(
        Wl2, Wr2, 512, 64, (__nv_bfloat16*)p_w2h, (__nv_bfloat16*)p_w2l);

    // layer-2 projections via mma.sync: g_xlr2 [N,128]
    {
        dim3 grid(128 / 64, (N_NODES + 127) / 128);
        gemm_mma_kernel<<<grid, 256, SM_TOT>>>(
            N_NODES, 512, 128,
            (const __nv_bfloat16*)p_hhi, (const __nv_bfloat16*)p_hlo,
            (const __nv_bfloat16*)p_w2h, (const __nv_bfloat16*)p_w2l,
            (float*)p_xlr2);
    }
    node2_fused_kernel<<<(N_NODES + 7) / 8, 256>>>(src, att2, b2, out);
}

// round 7
// speedup vs baseline: 2.4741x; 1.0121x over previous
#include <cuda_runtime.h>
#include <cuda_bf16.h>
#include <math_constants.h>
#include <cstdint>

// ---------------- problem constants ----------------
#define N_NODES 20000
#define N_EDGES 320000
#define F_IN    256
#define HIDC    64
#define HEADS   8
#define NCLS    64
#define HC1     (HEADS*HIDC)      // 512
#define NEG_SLOPE 0.2f
#define SM_EPS  1e-16f

typedef unsigned long long u64;

// ---------------- scratch (static device globals; no allocs) ----------------
__device__ float g_xlr1[(size_t)N_NODES * 1024];   // [N][xl1(512) | xr1(512)]
__device__ float g_h[(size_t)N_NODES * HC1];       // layer-1 output after ELU (fp32)
__device__ float g_xlr2[(size_t)N_NODES * 128];    // [N][xl2(64) | xr2(64)]
__device__ int   g_deg[N_NODES];
__device__ int   g_off[N_NODES + 1];
__device__ int   g_cur[N_NODES];
__device__ int   g_perm[N_EDGES];

// ---------------- helpers ----------------
__device__ __forceinline__ uint32_t smem_u32(const void* p) {
    uint32_t a;
    asm("{ .reg .u64 t; cvta.to.shared.u64 t, %1; cvt.u32.u64 %0, t; }" : "=r"(a) : "l"(p));
    return a;
}
#define SWZ128(o) ((o) ^ (((o) >> 3) & 0x70))

__device__ __forceinline__ void ldmx4(uint32_t* r, uint32_t addr) {
    asm volatile("ldmatrix.sync.aligned.m8n8.x4.shared.b16 {%0,%1,%2,%3}, [%4];"
                 : "=r"(r[0]), "=r"(r[1]), "=r"(r[2]), "=r"(r[3]) : "r"(addr));
}
__device__ __forceinline__ void ldmx4t(uint32_t* r, uint32_t addr) {
    asm volatile("ldmatrix.sync.aligned.m8n8.x4.trans.shared.b16 {%0,%1,%2,%3}, [%4];"
                 : "=r"(r[0]), "=r"(r[1]), "=r"(r[2]), "=r"(r[3]) : "r"(addr));
}
__device__ __forceinline__ void mma16816(float* c, const uint32_t* a, uint32_t b0, uint32_t b1) {
    asm volatile("mma.sync.aligned.m16n8k16.row.col.f32.bf16.bf16.f32 "
                 "{%0,%1,%2,%3}, {%4,%5,%6,%7}, {%8,%9}, {%0,%1,%2,%3};"
                 : "+f"(c[0]), "+f"(c[1]), "+f"(c[2]), "+f"(c[3])
                 : "r"(a[0]), "r"(a[1]), "r"(a[2]), "r"(a[3]), "r"(b0), "r"(b1));
}
// split 4 fp32 -> 4 hi-bf16 (u64) + 4 lo-bf16 (u64)
__device__ __forceinline__ void split4(float4 v, u64& hi, u64& lo) {
    union { __nv_bfloat16 b[4]; u64 u; } H, L;
    float f0 = v.x, f1 = v.y, f2 = v.z, f3 = v.w;
    __nv_bfloat16 h0 = __float2bfloat16(f0), h1 = __float2bfloat16(f1);
    __nv_bfloat16 h2 = __float2bfloat16(f2), h3 = __float2bfloat16(f3);
    H.b[0] = h0; H.b[1] = h1; H.b[2] = h2; H.b[3] = h3;
    L.b[0] = __float2bfloat16(f0 - __bfloat162float(h0));
    L.b[1] = __float2bfloat16(f1 - __bfloat162float(h1));
    L.b[2] = __float2bfloat16(f2 - __bfloat162float(h2));
    L.b[3] = __float2bfloat16(f3 - __bfloat162float(h3));
    hi = H.u; lo = L.u;
}

// ---------------- CSR build ----------------
__global__ void hist_kernel(const int* __restrict__ dst) {
    int e = blockIdx.x * blockDim.x + threadIdx.x;
    if (e < N_EDGES) atomicAdd(&g_deg[dst[e]], 1);
}

__global__ void scan_kernel() {
    __shared__ int sums[1024];
    const int CH = (N_NODES + 1023) / 1024;
    int t = threadIdx.x;
    int base = t * CH;
    int s = 0;
    for (int i = 0; i < CH; i++) {
        int idx = base + i;
        if (idx < N_NODES) s += g_deg[idx];
    }
    sums[t] = s;
    __syncthreads();
    for (int d = 1; d < 1024; d <<= 1) {
        int v = (t >= d) ? sums[t - d] : 0;
        __syncthreads();
        sums[t] += v;
        __syncthreads();
    }
    int pre = (t == 0) ? 0 : sums[t - 1];
    for (int i = 0; i < CH; i++) {
        int idx = base + i;
        if (idx < N_NODES) {
            g_off[idx] = pre;
            g_cur[idx] = pre;
            pre += g_deg[idx];
        }
    }
    if (t == 0) g_off[N_NODES] = sums[1023];
}

__global__ void scatter_kernel(const int* __restrict__ dst) {
    int e = blockIdx.x * blockDim.x + threadIdx.x;
    if (e < N_EDGES) {
        int p = atomicAdd(&g_cur[dst[e]], 1);
        g_perm[p] = e;
    }
}

// ---------------- mma.sync split-bf16 GEMM, fused fp32->bf16 split ----------------
// C[by*128+r, bx*64+n] = sum_k A[r,k]*B[k,n]
// A: fp32 [M,K] row-major. B: original fp32 weights [K,N0] (B0 for n<N0, B1 for n>=N0).
// In-kernel: A split to hi/lo smem [m][k]; B split to hi/lo smem [k][n] (ldmatrix.trans).
#define SM_AHI  0
#define SM_ALO  16384
#define SM_BHI  32768
#define SM_BLO  40960
#define SM_TOT  49152

__global__ void __launch_bounds__(256) gemm_mma_kernel(
    int M, int K, int N0, int ldc,
    const float* __restrict__ A,
    const float* __restrict__ B0, const float* __restrict__ B1,
    float* __restrict__ C)
{
    extern __shared__ char smem[];
    uint32_t sb = smem_u32(smem);
    const int tid = threadIdx.x, wid = tid >> 5, lane = tid & 31;
    const int by = blockIdx.y, bx = blockIdx.x;
    const int warpM = wid & 3, warpN = wid >> 2;   // 4 x 2 warp grid (warp tile 32x32)

    // B column window
    int nbase = bx * 64;
    const float* Bp = (nbase < N0) ? (B0 + nbase) : (B1 + (nbase - N0));

    float acc[2][4][4];
#pragma unroll
    for (int a = 0; a < 2; a++)
#pragma unroll
        for (int b = 0; b < 4; b++)
#pragma unroll
            for (int c = 0; c < 4; c++) acc[a][b][c] = 0.f;

    const int nchunks = K >> 6;
    for (int ch = 0; ch < nchunks; ch++) {
        int k0 = ch << 6;
        // A tile: 128 rows x 64 k fp32 -> hi/lo bf16 smem [m][k] (128B rows, swizzled)
        for (int i = tid; i < 2048; i += 256) {
            int row = i >> 4, g = (i & 15) << 2;
            int gr = by * 128 + row;
            float4 v = make_float4(0.f, 0.f, 0.f, 0.f);
            if (gr < M) v = *(const float4*)(A + (size_t)gr * K + k0 + g);
            u64 hi, lo;
            split4(v, hi, lo);
            uint32_t so = SWZ128(row * 128 + g * 2);
            *(u64*)(smem + SM_AHI + so) = hi;
            *(u64*)(smem + SM_ALO + so) = lo;
        }
        // B tile: 64 k-rows x 64 n fp32 -> hi/lo bf16 smem [k][n]
        for (int i = tid; i < 1024; i += 256) {
            int row = i >> 4, g = (i & 15) << 2;   // row = k offset, g = n offset
            float4 v = *(const float4*)(Bp + (size_t)(k0 + row) * N0 + g);
            u64 hi, lo;
            split4(v, hi, lo);
            uint32_t so = SWZ128(row * 128 + g * 2);
            *(u64*)(smem + SM_BHI + so) = hi;
            *(u64*)(smem + SM_BLO + so) = lo;
        }
        __syncthreads();

#pragma unroll
        for (int ks = 0; ks < 4; ks++) {
            uint32_t ahi[2][4], alo[2][4], bhi[2][4], blo[2][4];
            int colb = ks * 32 + (lane >> 4) * 16;
#pragma unroll
            for (int mt = 0; mt < 2; mt++) {
                uint32_t off = SWZ128((warpM * 32 + mt * 16 + (lane & 15)) * 128 + colb);
                ldmx4(ahi[mt], sb + SM_AHI + off);
                ldmx4(alo[mt], sb + SM_ALO + off);
            }
            // B via trans: rows = k (ks*16 + lane&15), byte col = n*2 (+16B for n-half)
#pragma unroll
            for (int nt = 0; nt < 2; nt++) {
                uint32_t off = SWZ128((ks * 16 + (lane & 15)) * 128
                                      + (warpN * 32 + nt * 16) * 2 + (lane >> 4) * 16);
                ldmx4t(bhi[nt], sb + SM_BHI + off);
                ldmx4t(blo[nt], sb + SM_BLO + off);
            }
#pragma unroll
            for (int mt = 0; mt < 2; mt++)
#pragma unroll
                for (int nt = 0; nt < 2; nt++)
#pragma unroll
                    for (int hf = 0; hf < 2; hf++) {
                        float* c = acc[mt][nt * 2 + hf];
                        // trans frags pair as (r0,r1) / (r2,r3)
                        mma16816(c, ahi[mt], bhi[nt][2 * hf], bhi[nt][2 * hf + 1]);
                        mma16816(c, ahi[mt], blo[nt][2 * hf], blo[nt][2 * hf + 1]);
                        mma16816(c, alo[mt], bhi[nt][2 * hf], bhi[nt][2 * hf + 1]);
                    }
        }
        __syncthreads();
    }

    // epilogue: stage fp32 tile in smem (aliases A region), coalesced store
    float* stage = (float*)(smem + SM_AHI);
    {
        int r0 = lane >> 2, cb = (lane & 3) * 2;
#pragma unroll
        for (int mt = 0; mt < 2; mt++)
#pragma unroll
            for (int j = 0; j < 4; j++) {
                int col = warpN * 32 + (j >> 1) * 16 + (j & 1) * 8 + cb;
                float* st = stage + (warpM * 32 + mt * 16 + r0) * 64 + col;
                st[0]          = acc[mt][j][0];
                st[1]          = acc[mt][j][1];
                st[8 * 64]     = acc[mt][j][2];
                st[8 * 64 + 1] = acc[mt][j][3];
            }
    }
    __syncthreads();
    for (int i = tid; i < 2048; i += 256) {
        int row = i >> 4, c4 = (i & 15) << 2;
        int gr = by * 128 + row;
        if (gr < M)
            *(float4*)(C + (size_t)gr * ldc + bx * 64 + c4) = *(float4*)(stage + row * 64 + c4);
    }
}

// ---------------- layer 1: fused, 2 warps per head (edge-split) ----------------
// 512 threads: wid&7 = head, wid>>3 = edge half. smem merge of partial states.
__global__ void __launch_bounds__(512) node1_fused_kernel(
    const int* __restrict__ src, const float* __restrict__ att1,
    const float* __restrict__ b1)
{
    __shared__ float4 mrg[8][32];
    int n = blockIdx.x;
    int wid = threadIdx.x >> 5, lane = threadIdx.x & 31;
    int h = wid & 7, half = wid >> 3;
    int beg = g_off[n], end = g_off[n + 1];
    int c0 = h * 64 + lane;

    float xr0 = g_xlr1[(size_t)n * 1024 + 512 + c0];
    float xr1 = g_xlr1[(size_t)n * 1024 + 512 + c0 + 32];
    float at0 = att1[c0], at1 = att1[c0 + 32];

    float m = -CUDART_INF_F, ssum = 0.f;
    float acc0 = 0.f, acc1 = 0.f;

    int i = beg + half;
    for (; i + 6 < end; i += 8) {
        const float* p0 = g_xlr1 + (size_t)src[g_perm[i + 0]] * 1024 + h * 64;
        const float* p1 = g_xlr1 + (size_t)src[g_perm[i + 2]] * 1024 + h * 64;
        const float* p2 = g_xlr1 + (size_t)src[g_perm[i + 4]] * 1024 + h * 64;
        const float* p3 = g_xlr1 + (size_t)src[g_perm[i + 6]] * 1024 + h * 64;
        float a0 = p0[lane], b0 = p0[lane + 32];
        float a1 = p1[lane], b1v = p1[lane + 32];
        float a2 = p2[lane], b2v = p2[lane + 32];
        float a3 = p3[lane], b3v = p3[lane + 32];

        float u, v;
        u = a0 + xr0; u = u > 0.f ? u : NEG_SLOPE * u;
        v = b0 + xr1; v = v > 0.f ? v : NEG_SLOPE * v;
        float s0 = at0 * u + at1 * v;
        u = a1 + xr0; u = u > 0.f ? u : NEG_SLOPE * u;
        v = b1v + xr1; v = v > 0.f ? v : NEG_SLOPE * v;
        float s1 = at0 * u + at1 * v;
        u = a2 + xr0; u = u > 0.f ? u : NEG_SLOPE * u;
        v = b2v + xr1; v = v > 0.f ? v : NEG_SLOPE * v;
        float s2 = at0 * u + at1 * v;
        u = a3 + xr0; u = u > 0.f ? u : NEG_SLOPE * u;
        v = b3v + xr1; v = v > 0.f ? v : NEG_SLOPE * v;
        float s3 = at0 * u + at1 * v;

#pragma unroll
        for (int o = 16; o; o >>= 1) {
            s0 += __shfl_xor_sync(0xffffffffu, s0, o);
            s1 += __shfl_xor_sync(0xffffffffu, s1, o);
            s2 += __shfl_xor_sync(0xffffffffu, s2, o);
            s3 += __shfl_xor_sync(0xffffffffu, s3, o);
        }

        float mn = fmaxf(fmaxf(fmaxf(s0, s1), fmaxf(s2, s3)), m);
        float scale = __expf(m - mn);
        float w0 = __expf(s0 - mn), w1 = __expf(s1 - mn);
        float w2 = __expf(s2 - mn), w3 = __expf(s3 - mn);
        ssum = ssum * scale + ((w0 + w1) + (w2 + w3));
        acc0 = acc0 * scale + ((w0 * a0 + w1 * a1) + (w2 * a2 + w3 * a3));
        acc1 = acc1 * scale + ((w0 * b0 + w1 * b1v) + (w2 * b2v + w3 * b3v));
        m = mn;
    }
    for (; i < end; i += 2) {
        const float* p = g_xlr1 + (size_t)src[g_perm[i]] * 1024 + h * 64;
        float x0 = p[lane], x1 = p[lane + 32];
        float u = x0 + xr0; u = u > 0.f ? u : NEG_SLOPE * u;
        float v = x1 + xr1; v = v > 0.f ? v : NEG_SLOPE * v;
        float s = at0 * u + at1 * v;
#pragma unroll
        for (int o = 16; o; o >>= 1) s += __shfl_xor_sync(0xffffffffu, s, o);
        float mn = fmaxf(m, s);
        float scale = __expf(m - mn);
        float es = __expf(s - mn);
        ssum = ssum * scale + es;
        acc0 = acc0 * scale + es * x0;
        acc1 = acc1 * scale + es * x1;
        m = mn;
    }

    if (half == 1) mrg[h][lane] = make_float4(m, ssum, acc0, acc1);
    __syncthreads();
    if (half == 0) {
        float4 o = mrg[h][lane];
        float mn = fmaxf(m, o.x);
        if (mn < -1e37f) mn = 0.f;   // deg-0 node
        float sc0 = __expf(m - mn), sc1 = __expf(o.x - mn);
        ssum = ssum * sc0 + o.y * sc1;
        acc0 = acc0 * sc0 + o.z * sc1;
        acc1 = acc1 * sc0 + o.w * sc1;

        float inv = 1.f / (ssum + SM_EPS);
        float v0 = acc0 * inv + b1[c0];
        float v1 = acc1 * inv + b1[c0 + 32];
        g_h[(size_t)n * HC1 + c0]      = v0 > 0.f ? v0 : __expf(v0) - 1.f;
        g_h[(size_t)n * HC1 + c0 + 32] = v1 > 0.f ? v1 : __expf(v1) - 1.f;
    }
}

// ---------------- layer 2: fused, 2 warps per node (edge-split) ----------------
// 512 threads: 8 nodes per block, wid&7 = node slot, wid>>3 = edge half.
__global__ void __launch_bounds__(512) node2_fused_kernel(
    const int* __restrict__ src, const float* __restrict__ att2,
    const float* __restrict__ b2, float* __restrict__ out)
{
    __shared__ float4 mrg[8][32];
    int wid = threadIdx.x >> 5, lane = threadIdx.x & 31;
    int slot = wid & 7, half = wid >> 3;
    int n = blockIdx.x * 8 + slot;
    if (n >= N_NODES) return;
    int beg = g_off[n], end = g_off[n + 1];

    float xr0 = g_xlr2[(size_t)n * 128 + 64 + lane];
    float xr1 = g_xlr2[(size_t)n * 128 + 64 + lane + 32];
    float at0 = att2[lane], at1 = att2[lane + 32];

    float m = -CUDART_INF_F, ssum = 0.f;
    float acc0 = 0.f, acc1 = 0.f;

    int i = beg + half;
    for (; i + 6 < end; i += 8) {
        const float* p0 = g_xlr2 + (size_t)src[g_perm[i + 0]] * 128;
        const float* p1 = g_xlr2 + (size_t)src[g_perm[i + 2]] * 128;
        const float* p2 = g_xlr2 + (size_t)src[g_perm[i + 4]] * 128;
        const float* p3 = g_xlr2 + (size_t)src[g_perm[i + 6]] * 128;
        float a0 = p0[lane], b0 = p0[lane + 32];
        float a1 = p1[lane], b1v = p1[lane + 32];
        float a2 = p2[lane], b2v = p2[lane + 32];
        float a3 = p3[lane], b3v = p3[lane + 32];

        float u, v;
        u = a0 + xr0; u = u > 0.f ? u : NEG_SLOPE * u;
        v = b0 + xr1; v = v > 0.f ? v : NEG_SLOPE * v;
        float s0 = at0 * u + at1 * v;
        u = a1 + xr0; u = u > 0.f ? u : NEG_SLOPE * u;
        v = b1v + xr1; v = v > 0.f ? v : NEG_SLOPE * v;
        float s1 = at0 * u + at1 * v;
        u = a2 + xr0; u = u > 0.f ? u : NEG_SLOPE * u;
        v = b2v + xr1; v = v > 0.f ? v : NEG_SLOPE * v;
        float s2 = at0 * u + at1 * v;
        u = a3 + xr0; u = u > 0.f ? u : NEG_SLOPE * u;
        v = b3v + xr1; v = v > 0.f ? v : NEG_SLOPE * v;
        float s3 = at0 * u + at1 * v;

#pragma unroll
        for (int o = 16; o; o >>= 1) {
            s0 += __shfl_xor_sync(0xffffffffu, s0, o);
            s1 += __shfl_xor_sync(0xffffffffu, s1, o);
            s2 += __shfl_xor_sync(0xffffffffu, s2, o);
            s3 += __shfl_xor_sync(0xffffffffu, s3, o);
        }

        float mn = fmaxf(fmaxf(fmaxf(s0, s1), fmaxf(s2, s3)), m);
        float scale = __expf(m - mn);
        float w0 = __expf(s0 - mn), w1 = __expf(s1 - mn);
        float w2 = __expf(s2 - mn), w3 = __expf(s3 - mn);
        ssum = ssum * scale + ((w0 + w1) + (w2 + w3));
        acc0 = acc0 * scale + ((w0 * a0 + w1 * a1) + (w2 * a2 + w3 * a3));
        acc1 = acc1 * scale + ((w0 * b0 + w1 * b1v) + (w2 * b2v + w3 * b3v));
        m = mn;
    }
    for (; i < end; i += 2) {
        const float* p = g_xlr2 + (size_t)src[g_perm[i]] * 128;
        float x0 = p[lane], x1 = p[lane + 32];
        float u = x0 + xr0; u = u > 0.f ? u : NEG_SLOPE * u;
        float v = x1 + xr1; v = v > 0.f ? v : NEG_SLOPE * v;
        float s = at0 * u + at1 * v;
#pragma unroll
        for (int o = 16; o; o >>= 1) s += __shfl_xor_sync(0xffffffffu, s, o);
        float mn = fmaxf(m, s);
        float scale = __expf(m - mn);
        float es = __expf(s - mn);
        ssum = ssum * scale + es;
        acc0 = acc0 * scale + es * x0;
        acc1 = acc1 * scale + es * x1;
        m = mn;
    }

    if (half == 1) mrg[slot][lane] = make_float4(m, ssum, acc0, acc1);
    __syncthreads();
    if (half == 0) {
        float4 o = mrg[slot][lane];
        float mn = fmaxf(m, o.x);
        if (mn < -1e37f) mn = 0.f;
        float sc0 = __expf(m - mn), sc1 = __expf(o.x - mn);
        ssum = ssum * sc0 + o.y * sc1;
        acc0 = acc0 * sc0 + o.z * sc1;
        acc1 = acc1 * sc0 + o.w * sc1;

        float inv = 1.f / (ssum + SM_EPS);
        out[(size_t)n * NCLS + lane]      = acc0 * inv + b2[lane];
        out[(size_t)n * NCLS + lane + 32] = acc1 * inv + b2[lane + 32];
    }
}

// ---------------- launch ----------------
extern "C" void kernel_launch(void* const* d_in, const int* in_sizes, int n_in,
                              void* d_out, int out_size)
{
    (void)in_sizes; (void)n_in; (void)out_size;
    const float* x    = (const float*)d_in[0];
    const int*   ei   = (const int*)d_in[1];
    const int*   src  = ei;
    const int*   dst  = ei + N_EDGES;
    const float* Wl1  = (const float*)d_in[2];
    const float* Wr1  = (const float*)d_in[3];
    const float* att1 = (const float*)d_in[4];
    const float* b1   = (const float*)d_in[5];
    const float* Wl2  = (const float*)d_in[6];
    const float* Wr2  = (const float*)d_in[7];
    const float* att2 = (const float*)d_in[8];
    const float* b2   = (const float*)d_in[9];
    float* out = (float*)d_out;

    void *p_deg, *p_xlr1, *p_h, *p_xlr2;
    cudaGetSymbolAddress(&p_deg, g_deg);
    cudaGetSymbolAddress(&p_xlr1, g_xlr1);
    cudaGetSymbolAddress(&p_h, g_h);
    cudaGetSymbolAddress(&p_xlr2, g_xlr2);

    // CSR build
    cudaMemsetAsync(p_deg, 0, N_NODES * sizeof(int), 0);
    hist_kernel<<<(N_EDGES + 255) / 256, 256>>>(dst);
    scan_kernel<<<1, 1024>>>();
    scatter_kernel<<<(N_EDGES + 255) / 256, 256>>>(dst);

    // layer-1 projections (fused split): g_xlr1 [N,1024] = x @ [Wl1|Wr1]
    {
        dim3 grid(1024 / 64, (N_NODES + 127) / 128);
        gemm_mma_kernel<<<grid, 256, SM_TOT>>>(
            N_NODES, F_IN, 512, 1024, x, Wl1, Wr1, (float*)p_xlr1);
    }
    node1_fused_kernel<<<N_NODES, 512>>>(src, att1, b1);

    // layer-2 projections: g_xlr2 [N,128] = h @ [Wl2|Wr2]
    {
        dim3 grid(128 / 64, (N_NODES + 127) / 128);
        gemm_mma_kernel<<<grid, 256, SM_TOT>>>(
            N_NODES, HC1, 64, 128, (const float*)p_h, Wl2, Wr2, (float*)p_xlr2);
    }
    node2_fused_kernel<<<(N_NODES + 7) / 8, 512>>>(src, att2, b2, out);
}

// round 8
// speedup vs baseline: 2.7708x; 1.1199x over previous
#include <cuda_runtime.h>
#include <cuda_bf16.h>
#include <math_constants.h>
#include <cstdint>

// ---------------- problem constants ----------------
#define N_NODES 20000
#define N_EDGES 320000
#define F_IN    256
#define HIDC    64
#define HEADS   8
#define NCLS    64
#define HC1     (HEADS*HIDC)      // 512
#define NEG_SLOPE 0.2f
#define SM_EPS  1e-16f

typedef unsigned long long u64;

// ---------------- scratch (static device globals; no allocs) ----------------
__device__ float g_xlr1[(size_t)N_NODES * 1024];   // [N][xl1(512) | xr1(512)]
__device__ float g_xlr2[(size_t)N_NODES * 128];    // [N][xl2(64) | xr2(64)]
__device__ int   g_deg[N_NODES];
__device__ int   g_off[N_NODES + 1];
__device__ int   g_cur[N_NODES];
__device__ int   g_perm[N_EDGES];

// bf16 split operands
__device__ __nv_bfloat16 g_xhi[(size_t)N_NODES * F_IN];
__device__ __nv_bfloat16 g_xlo[(size_t)N_NODES * F_IN];
__device__ __nv_bfloat16 g_hhi[(size_t)N_NODES * HC1];   // written by node1 epilogue
__device__ __nv_bfloat16 g_hlo[(size_t)N_NODES * HC1];
__device__ __nv_bfloat16 g_wt1hi[1024 * 256];   // [Ntot=1024][K=256] (W^T, K-contig)
__device__ __nv_bfloat16 g_wt1lo[1024 * 256];
__device__ __nv_bfloat16 g_wt2hi[128 * 512];    // [Ntot=128][K=512]
__device__ __nv_bfloat16 g_wt2lo[128 * 512];

// ---------------- helpers ----------------
__device__ __forceinline__ uint32_t smem_u32(const void* p) {
    uint32_t a;
    asm("{ .reg .u64 t; cvta.to.shared.u64 t, %1; cvt.u32.u64 %0, t; }" : "=r"(a) : "l"(p));
    return a;
}
#define SWZ128(o) ((o) ^ (((o) >> 3) & 0x70))

__device__ __forceinline__ void cp16(uint32_t dst, const void* src) {
    asm volatile("cp.async.cg.shared.global [%0], [%1], 16;" :: "r"(dst), "l"(src));
}
__device__ __forceinline__ void cp_commit() {
    asm volatile("cp.async.commit_group;" ::: "memory");
}
template <int N>
__device__ __forceinline__ void cp_wait() {
    asm volatile("cp.async.wait_group %0;" :: "n"(N) : "memory");
}

__device__ __forceinline__ void ldmx4(uint32_t* r, uint32_t addr) {
    asm volatile("ldmatrix.sync.aligned.m8n8.x4.shared.b16 {%0,%1,%2,%3}, [%4];"
                 : "=r"(r[0]), "=r"(r[1]), "=r"(r[2]), "=r"(r[3]) : "r"(addr));
}
__device__ __forceinline__ void mma16816(float* c, const uint32_t* a, uint32_t b0, uint32_t b1) {
    asm volatile("mma.sync.aligned.m16n8k16.row.col.f32.bf16.bf16.f32 "
                 "{%0,%1,%2,%3}, {%4,%5,%6,%7}, {%8,%9}, {%0,%1,%2,%3};"
                 : "+f"(c[0]), "+f"(c[1]), "+f"(c[2]), "+f"(c[3])
                 : "r"(a[0]), "r"(a[1]), "r"(a[2]), "r"(a[3]), "r"(b0), "r"(b1));
}

// ---------------- CSR build ----------------
__global__ void hist_kernel(const int* __restrict__ dst) {
    int e = blockIdx.x * blockDim.x + threadIdx.x;
    if (e < N_EDGES) atomicAdd(&g_deg[dst[e]], 1);
}

__global__ void scan_kernel() {
    __shared__ int sums[1024];
    const int CH = (N_NODES + 1023) / 1024;
    int t = threadIdx.x;
    int base = t * CH;
    int s = 0;
    for (int i = 0; i < CH; i++) {
        int idx = base + i;
        if (idx < N_NODES) s += g_deg[idx];
    }
    sums[t] = s;
    __syncthreads();
    for (int d = 1; d < 1024; d <<= 1) {
        int v = (t >= d) ? sums[t - d] : 0;
        __syncthreads();
        sums[t] += v;
        __syncthreads();
    }
    int pre = (t == 0) ? 0 : sums[t - 1];
    for (int i = 0; i < CH; i++) {
        int idx = base + i;
        if (idx < N_NODES) {
            g_off[idx] = pre;
            g_cur[idx] = pre;
            pre += g_deg[idx];
        }
    }
    if (t == 0) g_off[N_NODES] = sums[1023];
}

__global__ void scatter_kernel(const int* __restrict__ dst) {
    int e = blockIdx.x * blockDim.x + threadIdx.x;
    if (e < N_EDGES) {
        int p = atomicAdd(&g_cur[dst[e]], 1);
        g_perm[p] = e;
    }
}

// ---------------- bf16 split kernels ----------------
__global__ void split_kernel(const float* __restrict__ src,
                             __nv_bfloat16* __restrict__ hi,
                             __nv_bfloat16* __restrict__ lo, int n) {
    int i = blockIdx.x * blockDim.x + threadIdx.x;
    if (i < n) {
        float v = src[i];
        __nv_bfloat16 h = __float2bfloat16(v);
        hi[i] = h;
        lo[i] = __float2bfloat16(v - __bfloat162float(h));
    }
}

// W0,W1: [K, N0] row-major each -> Wt [2*N0, K]
__global__ void wtsplit_kernel(const float* __restrict__ W0, const float* __restrict__ W1,
                               int K, int N0,
                               __nv_bfloat16* __restrict__ hi,
                               __nv_bfloat16* __restrict__ lo) {
    int i = blockIdx.x * blockDim.x + threadIdx.x;
    if (i >= 2 * N0 * K) return;
    int n = i / K, k = i % K;
    float v = (n < N0) ? W0[(size_t)k * N0 + n] : W1[(size_t)k * N0 + (n - N0)];
    __nv_bfloat16 h = __float2bfloat16(v);
    hi[(size_t)n * K + k] = h;
    lo[(size_t)n * K + k] = __float2bfloat16(v - __bfloat162float(h));
}

// ---------------- mma.sync split-bf16 GEMM, cp.async double-buffered ----------------
// C[by*128+r, bx*64+n] = sum_k A[r,k]*B[n,k];  A=[M,K] hi/lo bf16, B=[Ntot,K] hi/lo bf16.
// Buffer layout (per stage, 48KB): AHI 0, ALO 16384, BHI 32768, BLO 40960. Two stages.
#define BUF_AHI 0
#define BUF_ALO 16384
#define BUF_BHI 32768
#define BUF_BLO 40960
#define BUF_SZ  49152
#define SM_TOT  (2 * BUF_SZ)

__global__ void __launch_bounds__(256) gemm_mma_kernel(
    int M, int K, int ldc,
    const __nv_bfloat16* __restrict__ Ahi, const __nv_bfloat16* __restrict__ Alo,
    const __nv_bfloat16* __restrict__ Bhi, const __nv_bfloat16* __restrict__ Blo,
    float* __restrict__ C)
{
    extern __shared__ char smem[];
    uint32_t sb = smem_u32(smem);
    const int tid = threadIdx.x, wid = tid >> 5, lane = tid & 31;
    const int by = blockIdx.y, bx = blockIdx.x;
    const int warpM = wid & 3, warpN = wid >> 2;   // 4 x 2 warp grid (warp tile 32x32)

    float acc[2][4][4];
#pragma unroll
    for (int a = 0; a < 2; a++)
#pragma unroll
        for (int b = 0; b < 4; b++)
#pragma unroll
            for (int c = 0; c < 4; c++) acc[a][b][c] = 0.f;

    const int nchunks = K >> 6;

    // per-thread load coordinates (16B granules)
    const int arow = tid >> 1;               // A: 2 threads per row, 4 iters -> rows tid>>1 + 128? no:
    // A tile: 128 rows x 128B (hi) = 1024 granules; 4 per thread.
    // Use i = tid + 256*it: row = i>>3, g = (i&7)*8 elems.

    auto issue = [&](int ch) {
        uint32_t buf = sb + (uint32_t)(ch & 1) * BUF_SZ;
        int k0 = ch << 6;
#pragma unroll
        for (int it = 0; it < 4; it++) {
            int i = tid + 256 * it;
            int row = i >> 3, g = (i & 7) << 3;
            int gr = by * 128 + row;
            if (gr >= M) gr = M - 1;   // clamp: garbage rows never stored
            uint32_t so = SWZ128(row * 128 + g * 2);
            cp16(buf + BUF_AHI + so, Ahi + (size_t)gr * K + k0 + g);
            cp16(buf + BUF_ALO + so, Alo + (size_t)gr * K + k0 + g);
        }
#pragma unroll
        for (int it = 0; it < 2; it++) {
            int i = tid + 256 * it;
            int row = i >> 3, g = (i & 7) << 3;
            int gn = bx * 64 + row;
            uint32_t so = SWZ128(row * 128 + g * 2);
            cp16(buf + BUF_BHI + so, Bhi + (size_t)gn * K + k0 + g);
            cp16(buf + BUF_BLO + so, Blo + (size_t)gn * K + k0 + g);
        }
        cp_commit();
    };

    issue(0);
    for (int ch = 0; ch < nchunks; ch++) {
        if (ch + 1 < nchunks) {
            issue(ch + 1);
            cp_wait<1>();
        } else {
            cp_wait<0>();
        }
        __syncthreads();

        uint32_t buf = sb + (uint32_t)(ch & 1) * BUF_SZ;
#pragma unroll
        for (int ks = 0; ks < 4; ks++) {
            uint32_t ahi[2][4], alo[2][4], bhi[2][4], blo[2][4];
            int colb = ks * 32 + (lane >> 4) * 16;
#pragma unroll
            for (int mt = 0; mt < 2; mt++) {
                uint32_t off = SWZ128((warpM * 32 + mt * 16 + (lane & 15)) * 128 + colb);
                ldmx4(ahi[mt], buf + BUF_AHI + off);
                ldmx4(alo[mt], buf + BUF_ALO + off);
            }
#pragma unroll
            for (int nt = 0; nt < 2; nt++) {
                uint32_t off = SWZ128((warpN * 32 + nt * 16 + (lane & 15)) * 128 + colb);
                ldmx4(bhi[nt], buf + BUF_BHI + off);
                ldmx4(blo[nt], buf + BUF_BLO + off);
            }
#pragma unroll
            for (int mt = 0; mt < 2; mt++)
#pragma unroll
                for (int nt = 0; nt < 2; nt++)
#pragma unroll
                    for (int hf = 0; hf < 2; hf++) {
                        float* c = acc[mt][nt * 2 + hf];
                        mma16816(c, ahi[mt], bhi[nt][hf], bhi[nt][hf + 2]);
                        mma16816(c, ahi[mt], blo[nt][hf], blo[nt][hf + 2]);
                        mma16816(c, alo[mt], bhi[nt][hf], bhi[nt][hf + 2]);
                    }
        }
        __syncthreads();
    }

    // epilogue: stage fp32 tile in smem (buffer 0), coalesced store
    float* stage = (float*)smem;
    {
        int r0 = lane >> 2, cb = (lane & 3) * 2;
#pragma unroll
        for (int mt = 0; mt < 2; mt++)
#pragma unroll
            for (int j = 0; j < 4; j++) {
                int col = warpN * 32 + (j >> 1) * 16 + (j & 1) * 8 + cb;
                float* st = stage + (warpM * 32 + mt * 16 + r0) * 64 + col;
                st[0]          = acc[mt][j][0];
                st[1]          = acc[mt][j][1];
                st[8 * 64]     = acc[mt][j][2];
                st[8 * 64 + 1] = acc[mt][j][3];
            }
    }
    __syncthreads();
    for (int i = tid; i < 2048; i += 256) {
        int row = i >> 4, c4 = (i & 15) << 2;
        int gr = by * 128 + row;
        if (gr < M)
            *(float4*)(C + (size_t)gr * ldc + bx * 64 + c4) = *(float4*)(stage + row * 64 + c4);
    }
}

// ---------------- layer 1: fused, 2 warps per head (edge-split), bf16 hi/lo epilogue ----------------
__global__ void __launch_bounds__(512) node1_fused_kernel(
    const int* __restrict__ src, const float* __restrict__ att1,
    const float* __restrict__ b1)
{
    __shared__ float4 mrg[8][32];
    int n = blockIdx.x;
    int wid = threadIdx.x >> 5, lane = threadIdx.x & 31;
    int h = wid & 7, half = wid >> 3;
    int beg = g_off[n], end = g_off[n + 1];
    int c0 = h * 64 + lane;

    float xr0 = g_xlr1[(size_t)n * 1024 + 512 + c0];
    float xr1 = g_xlr1[(size_t)n * 1024 + 512 + c0 + 32];
    float at0 = att1[c0], at1 = att1[c0 + 32];

    float m = -CUDART_INF_F, ssum = 0.f;
    float acc0 = 0.f, acc1 = 0.f;

    int i = beg + half;
    for (; i + 6 < end; i += 8) {
        const float* p0 = g_xlr1 + (size_t)src[g_perm[i + 0]] * 1024 + h * 64;
        const float* p1 = g_xlr1 + (size_t)src[g_perm[i + 2]] * 1024 + h * 64;
        const float* p2 = g_xlr1 + (size_t)src[g_perm[i + 4]] * 1024 + h * 64;
        const float* p3 = g_xlr1 + (size_t)src[g_perm[i + 6]] * 1024 + h * 64;
        float a0 = p0[lane], b0 = p0[lane + 32];
        float a1 = p1[lane], b1v = p1[lane + 32];
        float a2 = p2[lane], b2v = p2[lane + 32];
        float a3 = p3[lane], b3v = p3[lane + 32];

        float u, v;
        u = a0 + xr0; u = u > 0.f ? u : NEG_SLOPE * u;
        v = b0 + xr1; v = v > 0.f ? v : NEG_SLOPE * v;
        float s0 = at0 * u + at1 * v;
        u = a1 + xr0; u = u > 0.f ? u : NEG_SLOPE * u;
        v = b1v + xr1; v = v > 0.f ? v : NEG_SLOPE * v;
        float s1 = at0 * u + at1 * v;
        u = a2 + xr0; u = u > 0.f ? u : NEG_SLOPE * u;
        v = b2v + xr1; v = v > 0.f ? v : NEG_SLOPE * v;
        float s2 = at0 * u + at1 * v;
        u = a3 + xr0; u = u > 0.f ? u : NEG_SLOPE * u;
        v = b3v + xr1; v = v > 0.f ? v : NEG_SLOPE * v;
        float s3 = at0 * u + at1 * v;

#pragma unroll
        for (int o = 16; o; o >>= 1) {
            s0 += __shfl_xor_sync(0xffffffffu, s0, o);
            s1 += __shfl_xor_sync(0xffffffffu, s1, o);
            s2 += __shfl_xor_sync(0xffffffffu, s2, o);
            s3 += __shfl_xor_sync(0xffffffffu, s3, o);
        }

        float mn = fmaxf(fmaxf(fmaxf(s0, s1), fmaxf(s2, s3)), m);
        float scale = __expf(m - mn);
        float w0 = __expf(s0 - mn), w1 = __expf(s1 - mn);
        float w2 = __expf(s2 - mn), w3 = __expf(s3 - mn);
        ssum = ssum * scale + ((w0 + w1) + (w2 + w3));
        acc0 = acc0 * scale + ((w0 * a0 + w1 * a1) + (w2 * a2 + w3 * a3));
        acc1 = acc1 * scale + ((w0 * b0 + w1 * b1v) + (w2 * b2v + w3 * b3v));
        m = mn;
    }
    for (; i < end; i += 2) {
        const float* p = g_xlr1 + (size_t)src[g_perm[i]] * 1024 + h * 64;
        float x0 = p[lane], x1 = p[lane + 32];
        float u = x0 + xr0; u = u > 0.f ? u : NEG_SLOPE * u;
        float v = x1 + xr1; v = v > 0.f ? v : NEG_SLOPE * v;
        float s = at0 * u + at1 * v;
#pragma unroll
        for (int o = 16; o; o >>= 1) s += __shfl_xor_sync(0xffffffffu, s, o);
        float mn = fmaxf(m, s);
        float scale = __expf(m - mn);
        float es = __expf(s - mn);
        ssum = ssum * scale + es;
        acc0 = acc0 * scale + es * x0;
        acc1 = acc1 * scale + es * x1;
        m = mn;
    }

    if (half == 1) mrg[h][lane] = make_float4(m, ssum, acc0, acc1);
    __syncthreads();
    if (half == 0) {
        float4 o = mrg[h][lane];
        float mn = fmaxf(m, o.x);
        if (mn < -1e37f) mn = 0.f;   // deg-0 node
        float sc0 = __expf(m - mn), sc1 = __expf(o.x - mn);
        ssum = ssum * sc0 + o.y * sc1;
        acc0 = acc0 * sc0 + o.z * sc1;
        acc1 = acc1 * sc0 + o.w * sc1;

        float inv = 1.f / (ssum + SM_EPS);
        float v0 = acc0 * inv + b1[c0];
        float v1 = acc1 * inv + b1[c0 + 32];
        v0 = v0 > 0.f ? v0 : __expf(v0) - 1.f;
        v1 = v1 > 0.f ? v1 : __expf(v1) - 1.f;
        size_t o0 = (size_t)n * HC1 + c0, o1 = o0 + 32;
        __nv_bfloat16 h0 = __float2bfloat16(v0), h1 = __float2bfloat16(v1);
        g_hhi[o0] = h0; g_hlo[o0] = __float2bfloat16(v0 - __bfloat162float(h0));
        g_hhi[o1] = h1; g_hlo[o1] = __float2bfloat16(v1 - __bfloat162float(h1));
    }
}

// ---------------- layer 2: fused, 2 warps per node (edge-split) ----------------
__global__ void __launch_bounds__(512) node2_fused_kernel(
    const int* __restrict__ src, const float* __restrict__ att2,
    const float* __restrict__ b2, float* __restrict__ out)
{
    __shared__ float4 mrg[8][32];
    int wid = threadIdx.x >> 5, lane = threadIdx.x & 31;
    int slot = wid & 7, half = wid >> 3;
    int n = blockIdx.x * 8 + slot;
    if (n >= N_NODES) return;
    int beg = g_off[n], end = g_off[n + 1];

    float xr0 = g_xlr2[(size_t)n * 128 + 64 + lane];
    float xr1 = g_xlr2[(size_t)n * 128 + 64 + lane + 32];
    float at0 = att2[lane], at1 = att2[lane + 32];

    float m = -CUDART_INF_F, ssum = 0.f;
    float acc0 = 0.f, acc1 = 0.f;

    int i = beg + half;
    for (; i + 6 < end; i += 8) {
        const float* p0 = g_xlr2 + (size_t)src[g_perm[i + 0]] * 128;
        const float* p1 = g_xlr2 + (size_t)src[g_perm[i + 2]] * 128;
        const float* p2 = g_xlr2 + (size_t)src[g_perm[i + 4]] * 128;
        const float* p3 = g_xlr2 + (size_t)src[g_perm[i + 6]] * 128;
        float a0 = p0[lane], b0 = p0[lane + 32];
        float a1 = p1[lane], b1v = p1[lane + 32];
        float a2 = p2[lane], b2v = p2[lane + 32];
        float a3 = p3[lane], b3v = p3[lane + 32];

        float u, v;
        u = a0 + xr0; u = u > 0.f ? u : NEG_SLOPE * u;
        v = b0 + xr1; v = v > 0.f ? v : NEG_SLOPE * v;
        float s0 = at0 * u + at1 * v;
        u = a1 + xr0; u = u > 0.f ? u : NEG_SLOPE * u;
        v = b1v + xr1; v = v > 0.f ? v : NEG_SLOPE * v;
        float s1 = at0 * u + at1 * v;
        u = a2 + xr0; u = u > 0.f ? u : NEG_SLOPE * u;
        v = b2v + xr1; v = v > 0.f ? v : NEG_SLOPE * v;
        float s2 = at0 * u + at1 * v;
        u = a3 + xr0; u = u > 0.f ? u : NEG_SLOPE * u;
        v = b3v + xr1; v = v > 0.f ? v : NEG_SLOPE * v;
        float s3 = at0 * u + at1 * v;

#pragma unroll
        for (int o = 16; o; o >>= 1) {
            s0 += __shfl_xor_sync(0xffffffffu, s0, o);
            s1 += __shfl_xor_sync(0xffffffffu, s1, o);
            s2 += __shfl_xor_sync(0xffffffffu, s2, o);
            s3 += __shfl_xor_sync(0xffffffffu, s3, o);
        }

        float mn = fmaxf(fmaxf(fmaxf(s0, s1), fmaxf(s2, s3)), m);
        float scale = __expf(m - mn);
        float w0 = __expf(s0 - mn), w1 = __expf(s1 - mn);
        float w2 = __expf(s2 - mn), w3 = __expf(s3 - mn);
        ssum = ssum * scale + ((w0 + w1) + (w2 + w3));
        acc0 = acc0 * scale + ((w0 * a0 + w1 * a1) + (w2 * a2 + w3 * a3));
        acc1 = acc1 * scale + ((w0 * b0 + w1 * b1v) + (w2 * b2v + w3 * b3v));
        m = mn;
    }
    for (; i < end; i += 2) {
        const float* p = g_xlr2 + (size_t)src[g_perm[i]] * 128;
        float x0 = p[lane], x1 = p[lane + 32];
        float u = x0 + xr0; u = u > 0.f ? u : NEG_SLOPE * u;
        float v = x1 + xr1; v = v > 0.f ? v : NEG_SLOPE * v;
        float s = at0 * u + at1 * v;
#pragma unroll
        for (int o = 16; o; o >>= 1) s += __shfl_xor_sync(0xffffffffu, s, o);
        float mn = fmaxf(m, s);
        float scale = __expf(m - mn);
        float es = __expf(s - mn);
        ssum = ssum * scale + es;
        acc0 = acc0 * scale + es * x0;
        acc1 = acc1 * scale + es * x1;
        m = mn;
    }

    if (half == 1) mrg[slot][lane] = make_float4(m, ssum, acc0, acc1);
    __syncthreads();
    if (half == 0) {
        float4 o = mrg[slot][lane];
        float mn = fmaxf(m, o.x);
        if (mn < -1e37f) mn = 0.f;
        float sc0 = __expf(m - mn), sc1 = __expf(o.x - mn);
        ssum = ssum * sc0 + o.y * sc1;
        acc0 = acc0 * sc0 + o.z * sc1;
        acc1 = acc1 * sc0 + o.w * sc1;

        float inv = 1.f / (ssum + SM_EPS);
        out[(size_t)n * NCLS + lane]      = acc0 * inv + b2[lane];
        out[(size_t)n * NCLS + lane + 32] = acc1 * inv + b2[lane + 32];
    }
}

// ---------------- launch ----------------
extern "C" void kernel_launch(void* const* d_in, const int* in_sizes, int n_in,
                              void* d_out, int out_size)
{
    (void)in_sizes; (void)n_in; (void)out_size;
    const float* x    = (const float*)d_in[0];
    const int*   ei   = (const int*)d_in[1];
    const int*   src  = ei;
    const int*   dst  = ei + N_EDGES;
    const float* Wl1  = (const float*)d_in[2];
    const float* Wr1  = (const float*)d_in[3];
    const float* att1 = (const float*)d_in[4];
    const float* b1   = (const float*)d_in[5];
    const float* Wl2  = (const float*)d_in[6];
    const float* Wr2  = (const float*)d_in[7];
    const float* att2 = (const float*)d_in[8];
    const float* b2   = (const float*)d_in[9];
    float* out = (float*)d_out;

    cudaFuncSetAttribute(gemm_mma_kernel, cudaFuncAttributeMaxDynamicSharedMemorySize, SM_TOT);

    void *p_deg, *p_xlr1, *p_xlr2;
    void *p_xhi, *p_xlo, *p_hhi, *p_hlo, *p_w1h, *p_w1l, *p_w2h, *p_w2l;
    cudaGetSymbolAddress(&p_deg, g_deg);
    cudaGetSymbolAddress(&p_xlr1, g_xlr1);
    cudaGetSymbolAddress(&p_xlr2, g_xlr2);
    cudaGetSymbolAddress(&p_xhi, g_xhi);
    cudaGetSymbolAddress(&p_xlo, g_xlo);
    cudaGetSymbolAddress(&p_hhi, g_hhi);
    cudaGetSymbolAddress(&p_hlo, g_hlo);
    cudaGetSymbolAddress(&p_w1h, g_wt1hi);
    cudaGetSymbolAddress(&p_w1l, g_wt1lo);
    cudaGetSymbolAddress(&p_w2h, g_wt2hi);
    cudaGetSymbolAddress(&p_w2l, g_wt2lo);

    // CSR build
    cudaMemsetAsync(p_deg, 0, N_NODES * sizeof(int), 0);
    hist_kernel<<<(N_EDGES + 255) / 256, 256>>>(dst);
    scan_kernel<<<1, 1024>>>();
    scatter_kernel<<<(N_EDGES + 255) / 256, 256>>>(dst);

    // split x and weights (layer 1)
    split_kernel<<<(N_NODES * F_IN + 255) / 256, 256>>>(
        x, (__nv_bfloat16*)p_xhi, (__nv_bfloat16*)p_xlo, N_NODES * F_IN);
    wtsplit_kernel<<<(1024 * 256 + 255) / 256, 256>>>(
        Wl1, Wr1, 256, 512, (__nv_bfloat16*)p_w1h, (__nv_bfloat16*)p_w1l);

    // layer-1 projections: g_xlr1 [N,1024]
    {
        dim3 grid(1024 / 64, (N_NODES + 127) / 128);
        gemm_mma_kernel<<<grid, 256, SM_TOT>>>(
            N_NODES, 256, 1024,
            (const __nv_bfloat16*)p_xhi, (const __nv_bfloat16*)p_xlo,
            (const __nv_bfloat16*)p_w1h, (const __nv_bfloat16*)p_w1l,
            (float*)p_xlr1);
    }
    node1_fused_kernel<<<N_NODES, 512>>>(src, att1, b1);

    // weights (layer 2)
    wtsplit_kernel<<<(128 * 512 + 255) / 256, 256>>>(
        Wl2, Wr2, 512, 64, (__nv_bfloat16*)p_w2h, (__nv_bfloat16*)p_w2l);

    // layer-2 projections: g_xlr2 [N,128]
    {
        dim3 grid(128 / 64, (N_NODES + 127) / 128);
        gemm_mma_kernel<<<grid, 256, SM_TOT>>>(
            N_NODES, 512, 128,
            (const __nv_bfloat16*)p_hhi, (const __nv_bfloat16*)p_hlo,
            (const __nv_bfloat16*)p_w2h, (const __nv_bfloat16*)p_w2l,
            (float*)p_xlr2);
    }
    node2_fused_kernel<<<(N_NODES + 7) / 8, 512>>>(src, att2, b2, out);
}

// round 10
// speedup vs baseline: 2.8275x; 1.0205x over previous
#include <cuda_runtime.h>
#include <cuda_bf16.h>
#include <math_constants.h>
#include <cstdint>

// ---------------- problem constants ----------------
#define N_NODES 20000
#define N_EDGES 320000
#define F_IN    256
#define HIDC    64
#define HEADS   8
#define NCLS    64
#define HC1     (HEADS*HIDC)      // 512
#define NEG_SLOPE 0.2f
#define SM_EPS  1e-16f

typedef unsigned long long u64;

// ---------------- scratch (static device globals; no allocs) ----------------
__device__ float g_xlr1[(size_t)N_NODES * 1024];   // [N][xl1(512) | xr1(512)]
__device__ float g_xlr2[(size_t)N_NODES * 128];    // [N][xl2(64) | xr2(64)]
__device__ int   g_deg[N_NODES];
__device__ int   g_off[N_NODES + 1];
__device__ int   g_cur[N_NODES];
__device__ int   g_esrc[N_EDGES];                  // CSR-ordered source node ids

// bf16 split operands
__device__ __nv_bfloat16 g_xhi[(size_t)N_NODES * F_IN];
__device__ __nv_bfloat16 g_xlo[(size_t)N_NODES * F_IN];
__device__ __nv_bfloat16 g_hhi[(size_t)N_NODES * HC1];   // written by node1 epilogue
__device__ __nv_bfloat16 g_hlo[(size_t)N_NODES * HC1];
__device__ __nv_bfloat16 g_wt1hi[1024 * 256];   // [Ntot=1024][K=256] (W^T, K-contig)
__device__ __nv_bfloat16 g_wt1lo[1024 * 256];
__device__ __nv_bfloat16 g_wt2hi[128 * 512];    // [Ntot=128][K=512]
__device__ __nv_bfloat16 g_wt2lo[128 * 512];

// ---------------- helpers ----------------
__device__ __forceinline__ uint32_t smem_u32(const void* p) {
    uint32_t a;
    asm("{ .reg .u64 t; cvta.to.shared.u64 t, %1; cvt.u32.u64 %0, t; }" : "=r"(a) : "l"(p));
    return a;
}
#define SWZ128(o) ((o) ^ (((o) >> 3) & 0x70))

__device__ __forceinline__ void cp16(uint32_t dst, const void* src) {
    asm volatile("cp.async.cg.shared.global [%0], [%1], 16;" :: "r"(dst), "l"(src));
}
__device__ __forceinline__ void cp_commit() {
    asm volatile("cp.async.commit_group;" ::: "memory");
}
template <int N>
__device__ __forceinline__ void cp_wait() {
    asm volatile("cp.async.wait_group %0;" :: "n"(N) : "memory");
}

__device__ __forceinline__ void ldmx4(uint32_t* r, uint32_t addr) {
    asm volatile("ldmatrix.sync.aligned.m8n8.x4.shared.b16 {%0,%1,%2,%3}, [%4];"
                 : "=r"(r[0]), "=r"(r[1]), "=r"(r[2]), "=r"(r[3]) : "r"(addr));
}
__device__ __forceinline__ void mma16816(float* c, const uint32_t* a, uint32_t b0, uint32_t b1) {
    asm volatile("mma.sync.aligned.m16n8k16.row.col.f32.bf16.bf16.f32 "
                 "{%0,%1,%2,%3}, {%4,%5,%6,%7}, {%8,%9}, {%0,%1,%2,%3};"
                 : "+f"(c[0]), "+f"(c[1]), "+f"(c[2]), "+f"(c[3])
                 : "r"(a[0]), "r"(a[1]), "r"(a[2]), "r"(a[3]), "r"(b0), "r"(b1));
}

// ---------------- CSR build ----------------
__global__ void hist_kernel(const int* __restrict__ dst) {
    int e = blockIdx.x * blockDim.x + threadIdx.x;
    if (e < N_EDGES) atomicAdd(&g_deg[dst[e]], 1);
}

__global__ void scan_kernel() {
    __shared__ int sums[1024];
    const int CH = (N_NODES + 1023) / 1024;
    int t = threadIdx.x;
    int base = t * CH;
    int s = 0;
    for (int i = 0; i < CH; i++) {
        int idx = base + i;
        if (idx < N_NODES) s += g_deg[idx];
    }
    sums[t] = s;
    __syncthreads();
    for (int d = 1; d < 1024; d <<= 1) {
        int v = (t >= d) ? sums[t - d] : 0;
        __syncthreads();
        sums[t] += v;
        __syncthreads();
    }
    int pre = (t == 0) ? 0 : sums[t - 1];
    for (int i = 0; i < CH; i++) {
        int idx = base + i;
        if (idx < N_NODES) {
            g_off[idx] = pre;
            g_cur[idx] = pre;
            pre += g_deg[idx];
        }
    }
    if (t == 0) g_off[N_NODES] = sums[1023];
}

__global__ void scatter_kernel(const int* __restrict__ src, const int* __restrict__ dst) {
    int e = blockIdx.x * blockDim.x + threadIdx.x;
    if (e < N_EDGES) {
        int p = atomicAdd(&g_cur[dst[e]], 1);
        g_esrc[p] = src[e];
    }
}

// ---------------- bf16 split kernels ----------------
__global__ void split_kernel(const float* __restrict__ src,
                             __nv_bfloat16* __restrict__ hi,
                             __nv_bfloat16* __restrict__ lo, int n) {
    int i = blockIdx.x * blockDim.x + threadIdx.x;
    if (i < n) {
        float v = src[i];
        __nv_bfloat16 h = __float2bfloat16(v);
        hi[i] = h;
        lo[i] = __float2bfloat16(v - __bfloat162float(h));
    }
}

// W0,W1: [K, N0] row-major each -> Wt [2*N0, K]
__global__ void wtsplit_kernel(const float* __restrict__ W0, const float* __restrict__ W1,
                               int K, int N0,
                               __nv_bfloat16* __restrict__ hi,
                               __nv_bfloat16* __restrict__ lo) {
    int i = blockIdx.x * blockDim.x + threadIdx.x;
    if (i >= 2 * N0 * K) return;
    int n = i / K, k = i % K;
    float v = (n < N0) ? W0[(size_t)k * N0 + n] : W1[(size_t)k * N0 + (n - N0)];
    __nv_bfloat16 h = __float2bfloat16(v);
    hi[(size_t)n * K + k] = h;
    lo[(size_t)n * K + k] = __float2bfloat16(v - __bfloat162float(h));
}

// ---------------- mma.sync split-bf16 GEMM, cp.async double-buffered ----------------
#define BUF_AHI 0
#define BUF_ALO 16384
#define BUF_BHI 32768
#define BUF_BLO 40960
#define BUF_SZ  49152
#define SM_TOT  (2 * BUF_SZ)

__global__ void __launch_bounds__(256) gemm_mma_kernel(
    int M, int K, int ldc,
    const __nv_bfloat16* __restrict__ Ahi, const __nv_bfloat16* __restrict__ Alo,
    const __nv_bfloat16* __restrict__ Bhi, const __nv_bfloat16* __restrict__ Blo,
    float* __restrict__ C)
{
    extern __shared__ char smem[];
    uint32_t sb = smem_u32(smem);
    const int tid = threadIdx.x, wid = tid >> 5, lane = tid & 31;
    const int by = blockIdx.y, bx = blockIdx.x;
    const int warpM = wid & 3, warpN = wid >> 2;

    float acc[2][4][4];
#pragma unroll
    for (int a = 0; a < 2; a++)
#pragma unroll
        for (int b = 0; b < 4; b++)
#pragma unroll
            for (int c = 0; c < 4; c++) acc[a][b][c] = 0.f;

    const int nchunks = K >> 6;

    auto issue = [&](int ch) {
        uint32_t buf = sb + (uint32_t)(ch & 1) * BUF_SZ;
        int k0 = ch << 6;
#pragma unroll
        for (int it = 0; it < 4; it++) {
            int i = tid + 256 * it;
            int row = i >> 3, g = (i & 7) << 3;
            int gr = by * 128 + row;
            if (gr >= M) gr = M - 1;
            uint32_t so = SWZ128(row * 128 + g * 2);
            cp16(buf + BUF_AHI + so, Ahi + (size_t)gr * K + k0 + g);
            cp16(buf + BUF_ALO + so, Alo + (size_t)gr * K + k0 + g);
        }
#pragma unroll
        for (int it = 0; it < 2; it++) {
            int i = tid + 256 * it;
            int row = i >> 3, g = (i & 7) << 3;
            int gn = bx * 64 + row;
            uint32_t so = SWZ128(row * 128 + g * 2);
            cp16(buf + BUF_BHI + so, Bhi + (size_t)gn * K + k0 + g);
            cp16(buf + BUF_BLO + so, Blo + (size_t)gn * K + k0 + g);
        }
        cp_commit();
    };

    issue(0);
    for (int ch = 0; ch < nchunks; ch++) {
        if (ch + 1 < nchunks) {
            issue(ch + 1);
            cp_wait<1>();
        } else {
            cp_wait<0>();
        }
        __syncthreads();

        uint32_t buf = sb + (uint32_t)(ch & 1) * BUF_SZ;
#pragma unroll
        for (int ks = 0; ks < 4; ks++) {
            uint32_t ahi[2][4], alo[2][4], bhi[2][4], blo[2][4];
            int colb = ks * 32 + (lane >> 4) * 16;
#pragma unroll
            for (int mt = 0; mt < 2; mt++) {
                uint32_t off = SWZ128((warpM * 32 + mt * 16 + (lane & 15)) * 128 + colb);
                ldmx4(ahi[mt], buf + BUF_AHI + off);
                ldmx4(alo[mt], buf + BUF_ALO + off);
            }
#pragma unroll
            for (int nt = 0; nt < 2; nt++) {
                uint32_t off = SWZ128((warpN * 32 + nt * 16 + (lane & 15)) * 128 + colb);
                ldmx4(bhi[nt], buf + BUF_BHI + off);
                ldmx4(blo[nt], buf + BUF_BLO + off);
            }
#pragma unroll
            for (int mt = 0; mt < 2; mt++)
#pragma unroll
                for (int nt = 0; nt < 2; nt++)
#pragma unroll
                    for (int hf = 0; hf < 2; hf++) {
                        float* c = acc[mt][nt * 2 + hf];
                        mma16816(c, ahi[mt], bhi[nt][hf], bhi[nt][hf + 2]);
                        mma16816(c, ahi[mt], blo[nt][hf], blo[nt][hf + 2]);
                        mma16816(c, alo[mt], bhi[nt][hf], bhi[nt][hf + 2]);
                    }
        }
        __syncthreads();
    }

    float* stage = (float*)smem;
    {
        int r0 = lane >> 2, cb = (lane & 3) * 2;
#pragma unroll
        for (int mt = 0; mt < 2; mt++)
#pragma unroll
            for (int j = 0; j < 4; j++) {
                int col = warpN * 32 + (j >> 1) * 16 + (j & 1) * 8 + cb;
                float* st = stage + (warpM * 32 + mt * 16 + r0) * 64 + col;
                st[0]          = acc[mt][j][0];
                st[1]          = acc[mt][j][1];
                st[8 * 64]     = acc[mt][j][2];
                st[8 * 64 + 1] = acc[mt][j][3];
            }
    }
    __syncthreads();
    for (int i = tid; i < 2048; i += 256) {
        int row = i >> 4, c4 = (i & 15) << 2;
        int gr = by * 128 + row;
        if (gr < M)
            *(float4*)(C + (size_t)gr * ldc + bx * 64 + c4) = *(float4*)(stage + row * 64 + c4);
    }
}

// ---------------- layer 1: fused node kernel, 1 warp/head, lane-parallel indices ----------------
__global__ void __launch_bounds__(256) node1_fused_kernel(
    const float* __restrict__ att1, const float* __restrict__ b1)
{
    int n = blockIdx.x;
    int h = threadIdx.x >> 5, lane = threadIdx.x & 31;
    int beg = g_off[n], end = g_off[n + 1];
    int c0 = h * 64 + lane;

    float xr0 = g_xlr1[(size_t)n * 1024 + 512 + c0];
    float xr1 = g_xlr1[(size_t)n * 1024 + 512 + c0 + 32];
    float at0 = att1[c0], at1 = att1[c0 + 32];

    float m = -CUDART_INF_F, ssum = 0.f, acc0 = 0.f, acc1 = 0.f;

    for (int r = beg; r < end; r += 32) {
        int cnt = min(32, end - r);
        int sidx = (lane < cnt) ? g_esrc[r + lane] : 0;
        for (int j = 0; j < cnt; j += 8) {
            float xa[8], xb[8], sc[8];
#pragma unroll
            for (int k = 0; k < 8; k++) {
                int sn = __shfl_sync(0xffffffffu, sidx, j + k);
                const float* p = g_xlr1 + (size_t)sn * 1024 + h * 64;
                bool valid = (j + k) < cnt;
                xa[k] = valid ? p[lane] : 0.f;
                xb[k] = valid ? p[lane + 32] : 0.f;
            }
#pragma unroll
            for (int k = 0; k < 8; k++) {
                float u = xa[k] + xr0; u = u > 0.f ? u : NEG_SLOPE * u;
                float v = xb[k] + xr1; v = v > 0.f ? v : NEG_SLOPE * v;
                sc[k] = at0 * u + at1 * v;
            }
#pragma unroll
            for (int o = 16; o; o >>= 1)
#pragma unroll
                for (int k = 0; k < 8; k++)
                    sc[k] += __shfl_xor_sync(0xffffffffu, sc[k], o);
            float mn = m;
#pragma unroll
            for (int k = 0; k < 8; k++)
                if ((j + k) < cnt) mn = fmaxf(mn, sc[k]);
            float scale = __expf(m - mn);
            float wsum = 0.f, a0 = 0.f, a1 = 0.f;
#pragma unroll
            for (int k = 0; k < 8; k++) {
                float w = ((j + k) < cnt) ? __expf(sc[k] - mn) : 0.f;
                wsum += w;
                a0 += w * xa[k];
                a1 += w * xb[k];
            }
            ssum = ssum * scale + wsum;
            acc0 = acc0 * scale + a0;
            acc1 = acc1 * scale + a1;
            m = mn;
        }
    }

    float inv = 1.f / (ssum + SM_EPS);
    float v0 = acc0 * inv + b1[c0];
    float v1 = acc1 * inv + b1[c0 + 32];
    v0 = v0 > 0.f ? v0 : __expf(v0) - 1.f;
    v1 = v1 > 0.f ? v1 : __expf(v1) - 1.f;
    size_t o0 = (size_t)n * HC1 + c0, o1 = o0 + 32;
    __nv_bfloat16 h0 = __float2bfloat16(v0), h1 = __float2bfloat16(v1);
    g_hhi[o0] = h0; g_hlo[o0] = __float2bfloat16(v0 - __bfloat162float(h0));
    g_hhi[o1] = h1; g_hlo[o1] = __float2bfloat16(v1 - __bfloat162float(h1));
}

// ---------------- layer 2: fused node kernel, 1 warp/node ----------------
__global__ void __launch_bounds__(256) node2_fused_kernel(
    const float* __restrict__ att2, const float* __restrict__ b2,
    float* __restrict__ out)
{
    int n = blockIdx.x * 8 + (threadIdx.x >> 5);
    if (n >= N_NODES) return;
    int lane = threadIdx.x & 31;
    int beg = g_off[n], end = g_off[n + 1];

    float xr0 = g_xlr2[(size_t)n * 128 + 64 + lane];
    float xr1 = g_xlr2[(size_t)n * 128 + 64 + lane + 32];
    float at0 = att2[lane], at1 = att2[lane + 32];

    float m = -CUDART_INF_F, ssum = 0.f, acc0 = 0.f, acc1 = 0.f;

    for (int r = beg; r < end; r += 32) {
        int cnt = min(32, end - r);
        int sidx = (lane < cnt) ? g_esrc[r + lane] : 0;
        for (int j = 0; j < cnt; j += 8) {
            float xa[8], xb[8], sc[8];
#pragma unroll
            for (int k = 0; k < 8; k++) {
                int sn = __shfl_sync(0xffffffffu, sidx, j + k);
                const float* p = g_xlr2 + (size_t)sn * 128;
                bool valid = (j + k) < cnt;
                xa[k] = valid ? p[lane] : 0.f;
                xb[k] = valid ? p[lane + 32] : 0.f;
            }
#pragma unroll
            for (int k = 0; k < 8; k++) {
                float u = xa[k] + xr0; u = u > 0.f ? u : NEG_SLOPE * u;
                float v = xb[k] + xr1; v = v > 0.f ? v : NEG_SLOPE * v;
                sc[k] = at0 * u + at1 * v;
            }
#pragma unroll
            for (int o = 16; o; o >>= 1)
#pragma unroll
                for (int k = 0; k < 8; k++)
                    sc[k] += __shfl_xor_sync(0xffffffffu, sc[k], o);
            float mn = m;
#pragma unroll
            for (int k = 0; k < 8; k++)
                if ((j + k) < cnt) mn = fmaxf(mn, sc[k]);
            float scale = __expf(m - mn);
            float wsum = 0.f, a0 = 0.f, a1 = 0.f;
#pragma unroll
            for (int k = 0; k < 8; k++) {
                float w = ((j + k) < cnt) ? __expf(sc[k] - mn) : 0.f;
                wsum += w;
                a0 += w * xa[k];
                a1 += w * xb[k];
            }
            ssum = ssum * scale + wsum;
            acc0 = acc0 * scale + a0;
            acc1 = acc1 * scale + a1;
            m = mn;
        }
    }

    float inv = 1.f / (ssum + SM_EPS);
    out[(size_t)n * NCLS + lane]      = acc0 * inv + b2[lane];
    out[(size_t)n * NCLS + lane + 32] = acc1 * inv + b2[lane + 32];
}

// ---------------- launch ----------------
extern "C" void kernel_launch(void* const* d_in, const int* in_sizes, int n_in,
                              void* d_out, int out_size)
{
    (void)in_sizes; (void)n_in; (void)out_size;
    const float* x    = (const float*)d_in[0];
    const int*   ei   = (const int*)d_in[1];
    const int*   src  = ei;
    const int*   dst  = ei + N_EDGES;
    const float* Wl1  = (const float*)d_in[2];
    const float* Wr1  = (const float*)d_in[3];
    const float* att1 = (const float*)d_in[4];
    const float* b1   = (const float*)d_in[5];
    const float* Wl2  = (const float*)d_in[6];
    const float* Wr2  = (const float*)d_in[7];
    const float* att2 = (const float*)d_in[8];
    const float* b2   = (const float*)d_in[9];
    float* out = (float*)d_out;

    cudaFuncSetAttribute(gemm_mma_kernel, cudaFuncAttributeMaxDynamicSharedMemorySize, SM_TOT);

    void *p_deg, *p_xlr1, *p_xlr2;
    void *p_xhi, *p_xlo, *p_hhi, *p_hlo, *p_w1h, *p_w1l, *p_w2h, *p_w2l;
    cudaGetSymbolAddress(&p_deg, g_deg);
    cudaGetSymbolAddress(&p_xlr1, g_xlr1);
    cudaGetSymbolAddress(&p_xlr2, g_xlr2);
    cudaGetSymbolAddress(&p_xhi, g_xhi);
    cudaGetSymbolAddress(&p_xlo, g_xlo);
    cudaGetSymbolAddress(&p_hhi, g_hhi);
    cudaGetSymbolAddress(&p_hlo, g_hlo);
    cudaGetSymbolAddress(&p_w1h, g_wt1hi);
    cudaGetSymbolAddress(&p_w1l, g_wt1lo);
    cudaGetSymbolAddress(&p_w2h, g_wt2hi);
    cudaGetSymbolAddress(&p_w2l, g_wt2lo);

    // CSR build (g_esrc = CSR-ordered src ids)
    cudaMemsetAsync(p_deg, 0, N_NODES * sizeof(int), 0);
    hist_kernel<<<(N_EDGES + 255) / 256, 256>>>(dst);
    scan_kernel<<<1, 1024>>>();
    scatter_kernel<<<(N_EDGES + 255) / 256, 256>>>(src, dst);

    // split x and weights (layer 1)
    split_kernel<<<(N_NODES * F_IN + 255) / 256, 256>>>(
        x, (__nv_bfloat16*)p_xhi, (__nv_bfloat16*)p_xlo, N_NODES * F_IN);
    wtsplit_kernel<<<(1024 * 256 + 255) / 256, 256>>>(
        Wl1, Wr1, 256, 512, (__nv_bfloat16*)p_w1h, (__nv_bfloat16*)p_w1l);

    // layer-1 projections: g_xlr1 [N,1024]
    {
        dim3 grid(1024 / 64, (N_NODES + 127) / 128);
        gemm_mma_kernel<<<grid, 256, SM_TOT>>>(
            N_NODES, 256, 1024,
            (const __nv_bfloat16*)p_xhi, (const __nv_bfloat16*)p_xlo,
            (const __nv_bfloat16*)p_w1h, (const __nv_bfloat16*)p_w1l,
            (float*)p_xlr1);
    }
    node1_fused_kernel<<<N_NODES, 256>>>(att1, b1);

    // weights (layer 2)
    wtsplit_kernel<<<(128 * 512 + 255) / 256, 256>>>(
        Wl2, Wr2, 512, 64, (__nv_bfloat16*)p_w2h, (__nv_bfloat16*)p_w2l);

    // layer-2 projections: g_xlr2 [N,128]
    {
        dim3 grid(128 / 64, (N_NODES + 127) / 128);
        gemm_mma_kernel<<<grid, 256, SM_TOT>>>(
            N_NODES, 512, 128,
            (const __nv_bfloat16*)p_hhi, (const __nv_bfloat16*)p_hlo,
            (const __nv_bfloat16*)p_w2h, (const __nv_bfloat16*)p_w2l,
            (float*)p_xlr2);
    }
    node2_fused_kernel<<<(N_NODES + 31) / 8 / 4 * 4, 256>>>(att2, b2, out);
}